// round 12
// baseline (speedup 1.0000x reference)
#include <cuda_runtime.h>
#include <cuda_fp16.h>
#include <math.h>
#include <stdint.h>

#define D_MODEL 1024
#define D_FF    4096
#define BATCH   4
#define SEQ     2048
#define NTOK    (BATCH * SEQ)   // 8192

// ---------------- scratch (allocation-free: __device__ globals) ----------------
__device__ __half g_norm1[(size_t)NTOK * D_MODEL];
__device__ __half g_norm1t[(size_t)NTOK * D_MODEL];      // per-batch [D][S]
__device__ __half g_scores[(size_t)BATCH * SEQ * SEQ];   // scores then probs
__device__ float  g_attn[(size_t)NTOK * D_MODEL];
__device__ float  g_x[(size_t)NTOK * D_MODEL];
__device__ __half g_norm2[(size_t)NTOK * D_MODEL];
__device__ __half g_h[(size_t)NTOK * D_FF];
__device__ __half g_w1t[(size_t)D_FF * D_MODEL];         // [ff][d]
__device__ __half g_w2t[(size_t)D_MODEL * D_FF];         // [d][ff]

// ---------------- reductions ----------------
__device__ __forceinline__ float block_sum(float v, float* sh) {
    int lane = threadIdx.x & 31, w = threadIdx.x >> 5;
    #pragma unroll
    for (int o = 16; o; o >>= 1) v += __shfl_down_sync(0xffffffffu, v, o);
    if (lane == 0) sh[w] = v;
    __syncthreads();
    if (w == 0) {
        float t = (lane < 8) ? sh[lane] : 0.f;
        #pragma unroll
        for (int o = 4; o; o >>= 1) t += __shfl_down_sync(0xffffffffu, t, o);
        if (lane == 0) sh[0] = t;
    }
    __syncthreads();
    float r = sh[0];
    __syncthreads();
    return r;
}

__device__ __forceinline__ float block_max(float v, float* sh) {
    int lane = threadIdx.x & 31, w = threadIdx.x >> 5;
    #pragma unroll
    for (int o = 16; o; o >>= 1) v = fmaxf(v, __shfl_down_sync(0xffffffffu, v, o));
    if (lane == 0) sh[w] = v;
    __syncthreads();
    if (w == 0) {
        float t = (lane < 8) ? sh[lane] : -3.4e38f;
        #pragma unroll
        for (int o = 4; o; o >>= 1) t = fmaxf(t, __shfl_down_sync(0xffffffffu, t, o));
        if (lane == 0) sh[0] = t;
    }
    __syncthreads();
    float r = sh[0];
    __syncthreads();
    return r;
}

// ---------------- LayerNorm (fp16 out) ----------------
__global__ __launch_bounds__(256) void ln_kernel(
    const float* __restrict__ in, const float* __restrict__ gamma,
    const float* __restrict__ beta, __half* __restrict__ out)
{
    __shared__ float sh[32];
    size_t row = blockIdx.x;
    const float* x = in + row * D_MODEL;
    float v[4], s = 0.f;
    #pragma unroll
    for (int i = 0; i < 4; i++) { v[i] = x[threadIdx.x + i * 256]; s += v[i]; }
    float mean = block_sum(s, sh) * (1.0f / D_MODEL);
    float q = 0.f;
    #pragma unroll
    for (int i = 0; i < 4; i++) { float d = v[i] - mean; q += d * d; }
    float var = block_sum(q, sh) * (1.0f / D_MODEL);
    float rstd = rsqrtf(var + 1e-5f);
    __half* y = out + row * D_MODEL;
    #pragma unroll
    for (int i = 0; i < 4; i++) {
        int c = threadIdx.x + i * 256;
        y[c] = __float2half_rn((v[i] - mean) * rstd * gamma[c] + beta[c]);
    }
}

// x fp32; norm2 fp16
__global__ __launch_bounds__(256) void add_ln_kernel(
    const float* __restrict__ src, const float* __restrict__ attn,
    const float* __restrict__ gamma, const float* __restrict__ beta,
    float* __restrict__ xout, __half* __restrict__ nout)
{
    __shared__ float sh[32];
    size_t row = blockIdx.x;
    const float* a = src + row * D_MODEL;
    const float* b = attn + row * D_MODEL;
    float v[4], s = 0.f;
    #pragma unroll
    for (int i = 0; i < 4; i++) {
        int c = threadIdx.x + i * 256;
        v[i] = a[c] + b[c];
        s += v[i];
    }
    float* xo = xout + row * D_MODEL;
    #pragma unroll
    for (int i = 0; i < 4; i++) xo[threadIdx.x + i * 256] = v[i];
    float mean = block_sum(s, sh) * (1.0f / D_MODEL);
    float q = 0.f;
    #pragma unroll
    for (int i = 0; i < 4; i++) { float d = v[i] - mean; q += d * d; }
    float var = block_sum(q, sh) * (1.0f / D_MODEL);
    float rstd = rsqrtf(var + 1e-5f);
    __half* y = nout + row * D_MODEL;
    #pragma unroll
    for (int i = 0; i < 4; i++) {
        int c = threadIdx.x + i * 256;
        y[c] = __float2half_rn((v[i] - mean) * rstd * gamma[c] + beta[c]);
    }
}

// ---------------- softmax over fp16 rows of length SEQ (in place) ----------------
__global__ __launch_bounds__(256) void softmax_kernel(__half* __restrict__ sc)
{
    __shared__ float sh[32];
    size_t row = blockIdx.x;
    __half* p = sc + row * (size_t)SEQ;
    float v[8], m = -3.4e38f;
    #pragma unroll
    for (int i = 0; i < 8; i++) { v[i] = __half2float(p[threadIdx.x + i * 256]); m = fmaxf(m, v[i]); }
    m = block_max(m, sh);
    float s = 0.f;
    #pragma unroll
    for (int i = 0; i < 8; i++) { v[i] = __expf(v[i] - m); s += v[i]; }
    s = block_sum(s, sh);
    float inv = 1.0f / s;
    #pragma unroll
    for (int i = 0; i < 8; i++) p[threadIdx.x + i * 256] = __float2half_rn(v[i] * inv);
}

// ---------------- tiled transpose + convert: out[C][R] = cvt(in[R][C])^T ------
template<typename TIN>
__global__ __launch_bounds__(256) void transpose_cvt(
    const TIN* __restrict__ in, __half* __restrict__ out,
    int R, int C, size_t sI, size_t sO)
{
    in += blockIdx.z * sI; out += blockIdx.z * sO;
    __shared__ float t[32][33];
    int tx = threadIdx.x & 31, ty = threadIdx.x >> 5;
    int c = blockIdx.x * 32 + tx;
    int r0 = blockIdx.y * 32;
    #pragma unroll
    for (int i = 0; i < 4; i++)
        t[ty + i * 8][tx] = (float)in[(size_t)(r0 + ty + i * 8) * C + c];
    __syncthreads();
    int rc = r0 + tx;
    int oc0 = blockIdx.x * 32;
    #pragma unroll
    for (int i = 0; i < 4; i++)
        out[(size_t)(oc0 + ty + i * 8) * R + rc] = __float2half_rn(t[tx][ty + i * 8]);
}

// ================ FP16 HMMA GEMM (NT, ldmatrix, BK=32, 256 thr) ===============
// C[M,N] = A[M,K] @ Bt[N,K]^T, fp16 operands, fp32 accumulate.
// Block 128x128, 256 threads = 8 warps (2 M x 4 N), warp tile 64x32,
// mma.sync.m16n8k16, BK=32 double-buffered, smem row stride 20 words:
//   LDSM phase banks 20r%32 distinct; STS.128 phase units 5r%8 distinct -> CF.
// EPI: 0 = scale*AB -> TOUT   1 = gelu(AB+bias) -> half   2 = AB+bias+resid -> float

__device__ __forceinline__ uint32_t smem_u32(const void* p) {
    uint32_t a;
    asm("{ .reg .u64 t; cvta.to.shared.u64 t, %1; cvt.u32.u64 %0, t; }" : "=r"(a) : "l"(p));
    return a;
}

__device__ __forceinline__ void ldsm4(uint32_t& r0, uint32_t& r1, uint32_t& r2, uint32_t& r3,
                                      uint32_t addr) {
    asm volatile("ldmatrix.sync.aligned.m8n8.x4.shared.b16 {%0,%1,%2,%3}, [%4];"
                 : "=r"(r0), "=r"(r1), "=r"(r2), "=r"(r3) : "r"(addr));
}

__device__ __forceinline__ void mma16(float* c, const uint32_t* a, const uint32_t* b) {
    asm volatile(
        "mma.sync.aligned.m16n8k16.row.col.f32.f16.f16.f32 "
        "{%0,%1,%2,%3}, {%4,%5,%6,%7}, {%8,%9}, {%0,%1,%2,%3};"
        : "+f"(c[0]), "+f"(c[1]), "+f"(c[2]), "+f"(c[3])
        : "r"(a[0]), "r"(a[1]), "r"(a[2]), "r"(a[3]), "r"(b[0]), "r"(b[1]));
}

__device__ __forceinline__ float gelu_exact(float v) {
    return v * 0.5f * (1.0f + erff(v * 0.70710678118654752f));
}

__device__ __forceinline__ void store2(__half* p, float a, float b) {
    *(__half2*)p = __floats2half2_rn(a, b);
}
__device__ __forceinline__ void store2(float* p, float a, float b) {
    p[0] = a; p[1] = b;
}

#define RSTR 20                       // smem row stride in 32-bit words
#define TILEW (128 * RSTR)            // words per tile buffer
#define TILEBYTES (TILEW * 4)         // 10240

template<int EPI, typename TOUT>
__global__ __launch_bounds__(256) void gemm_f16(
    const __half* __restrict__ A, const __half* __restrict__ Bt, TOUT* __restrict__ C,
    int K, int N, size_t sA, size_t sB, size_t sC,
    const float* __restrict__ bias, const float* __restrict__ resid, float scale)
{
    A += blockIdx.z * sA; Bt += blockIdx.z * sB; C += blockIdx.z * sC;
    if (EPI == 2) resid += blockIdx.z * sC;

    __shared__ uint32_t As[2][TILEW];
    __shared__ uint32_t Bs[2][TILEW];

    const int tid  = threadIdx.x;
    const int lane = tid & 31;
    const int warp = tid >> 5;
    const int warpM = warp >> 2;   // 0..1
    const int warpN = warp & 3;    // 0..3
    const int r  = lane >> 2;      // 0..7
    const int cq = lane & 3;       // 0..3

    const int row0 = blockIdx.y * 128;
    const int col0 = blockIdx.x * 128;

    // global load map: thread t -> row (t&127), 32B half (t>>7)
    const int lrow = tid & 127;
    const int lseg = tid >> 7;     // 0/1
    const __half* pa = A + (size_t)(row0 + lrow) * K + lseg * 16;
    const __half* pb = Bt + (size_t)(col0 + lrow) * K + lseg * 16;
    const int stsOff = lrow * RSTR + lseg * 8;   // words

    // ldmatrix lane addresses (buffer 0, sub-chunk 0)
    const uint32_t asBase = smem_u32(As);
    const uint32_t bsBase = smem_u32(Bs);
    uint32_t aAddr[4], bAddr[2];
    {
        int mrow = (lane & 7) + ((lane >> 3) & 1) * 8;   // row within 16
        int seg  = lane >> 4;                            // k segment 0/1
        #pragma unroll
        for (int i = 0; i < 4; i++) {
            int m = warpM * 64 + i * 16 + mrow;
            aAddr[i] = asBase + (uint32_t)(m * RSTR + seg * 4) * 4;
        }
        int nrow = (lane & 7) + ((lane >> 4) & 1) * 8;   // row within 16 (two j's)
        int bseg = (lane >> 3) & 1;
        #pragma unroll
        for (int jp = 0; jp < 2; jp++) {
            int n = warpN * 32 + jp * 16 + nrow;
            bAddr[jp] = bsBase + (uint32_t)(n * RSTR + bseg * 4) * 4;
        }
    }

    float acc[4][4][4] = {};
    uint4 ra[2], rb[2];

    auto ldg_tile = [&](int c) {
        const uint4* qa = (const uint4*)(pa + c * 32);
        const uint4* qb = (const uint4*)(pb + c * 32);
        ra[0] = qa[0]; ra[1] = qa[1];
        rb[0] = qb[0]; rb[1] = qb[1];
    };
    auto sts_tile = [&](int nb) {
        *(uint4*)&As[nb][stsOff]     = ra[0];
        *(uint4*)&As[nb][stsOff + 4] = ra[1];
        *(uint4*)&Bs[nb][stsOff]     = rb[0];
        *(uint4*)&Bs[nb][stsOff + 4] = rb[1];
    };

    ldg_tile(0);
    sts_tile(0);
    __syncthreads();

    const int nch = K / 32;
    int buf = 0;
    for (int c = 0; c < nch; c++) {
        const bool more = (c + 1 < nch);
        if (more) ldg_tile(c + 1);

        const uint32_t bo = (uint32_t)buf * TILEBYTES;
        #pragma unroll
        for (int s = 0; s < 2; s++) {
            const uint32_t so = bo + (uint32_t)s * 32;   // +8 words per sub-chunk
            uint32_t af[4][4], bf[4][2];
            #pragma unroll
            for (int i = 0; i < 4; i++)
                ldsm4(af[i][0], af[i][1], af[i][2], af[i][3], aAddr[i] + so);
            #pragma unroll
            for (int jp = 0; jp < 2; jp++)
                ldsm4(bf[2 * jp][0], bf[2 * jp][1], bf[2 * jp + 1][0], bf[2 * jp + 1][1],
                      bAddr[jp] + so);
            #pragma unroll
            for (int i = 0; i < 4; i++)
                #pragma unroll
                for (int j = 0; j < 4; j++)
                    mma16(acc[i][j], af[i], bf[j]);
        }

        if (more) {
            sts_tile(buf ^ 1);
            __syncthreads();
            buf ^= 1;
        }
    }

    // ---- epilogue ----
    #pragma unroll
    for (int i = 0; i < 4; i++) {
        int mrow = row0 + warpM * 64 + i * 16 + r;
        #pragma unroll
        for (int j = 0; j < 4; j++) {
            int ncol = col0 + warpN * 32 + j * 8 + 2 * cq;
            float v0 = acc[i][j][0], v1 = acc[i][j][1];
            float v2 = acc[i][j][2], v3 = acc[i][j][3];
            size_t p0 = (size_t)mrow * N + ncol;
            size_t p1 = (size_t)(mrow + 8) * N + ncol;
            if (EPI == 0) {
                v0 *= scale; v1 *= scale; v2 *= scale; v3 *= scale;
            } else {
                float bb0 = bias[ncol], bb1 = bias[ncol + 1];
                if (EPI == 1) {
                    v0 = gelu_exact(v0 + bb0); v1 = gelu_exact(v1 + bb1);
                    v2 = gelu_exact(v2 + bb0); v3 = gelu_exact(v3 + bb1);
                } else {
                    v0 += bb0 + resid[p0];     v1 += bb1 + resid[p0 + 1];
                    v2 += bb0 + resid[p1];     v3 += bb1 + resid[p1 + 1];
                }
            }
            store2(C + p0, v0, v1);
            store2(C + p1, v2, v3);
        }
    }
}

// ---------------- launch ----------------
extern "C" void kernel_launch(void* const* d_in, const int* in_sizes, int n_in,
                              void* d_out, int out_size)
{
    const float* src    = (const float*)d_in[0];
    const float* gamma1 = (const float*)d_in[1];
    const float* beta1  = (const float*)d_in[2];
    const float* gamma2 = (const float*)d_in[3];
    const float* beta2  = (const float*)d_in[4];
    const float* w1     = (const float*)d_in[5];
    const float* b1     = (const float*)d_in[6];
    const float* w2     = (const float*)d_in[7];
    const float* b2     = (const float*)d_in[8];
    float* out = (float*)d_out;

    __half *norm1, *norm1t, *scores, *norm2, *h, *w1t, *w2t;
    float *attn, *x;
    cudaGetSymbolAddress((void**)&norm1, g_norm1);
    cudaGetSymbolAddress((void**)&norm1t, g_norm1t);
    cudaGetSymbolAddress((void**)&scores, g_scores);
    cudaGetSymbolAddress((void**)&attn, g_attn);
    cudaGetSymbolAddress((void**)&x, g_x);
    cudaGetSymbolAddress((void**)&norm2, g_norm2);
    cudaGetSymbolAddress((void**)&h, g_h);
    cudaGetSymbolAddress((void**)&w1t, g_w1t);
    cudaGetSymbolAddress((void**)&w2t, g_w2t);

    const size_t SD = (size_t)SEQ * D_MODEL;
    const size_t SS = (size_t)SEQ * SEQ;

    // 0. weight transpose + fp16 convert: w1t[ff][d], w2t[d][ff]
    transpose_cvt<float><<<dim3(D_FF / 32, D_MODEL / 32, 1), 256>>>(w1, w1t, D_MODEL, D_FF, 0, 0);
    transpose_cvt<float><<<dim3(D_MODEL / 32, D_FF / 32, 1), 256>>>(w2, w2t, D_FF, D_MODEL, 0, 0);

    // 1. norm1 = LN(src) -> fp16
    ln_kernel<<<NTOK, 256>>>(src, gamma1, beta1, norm1);

    // 1b. norm1t[b] = norm1[b]^T  ([D][S] per batch, fp16)
    transpose_cvt<__half><<<dim3(D_MODEL / 32, SEQ / 32, BATCH), 256>>>(
        norm1, norm1t, SEQ, D_MODEL, SD, SD);

    // 2. scores[b] = norm1[b] @ norm1[b]^T / 32  -> fp16
    gemm_f16<0, __half><<<dim3(SEQ / 128, SEQ / 128, BATCH), 256>>>(
        norm1, norm1, scores, D_MODEL, SEQ, SD, SD, SS, nullptr, nullptr, 0.03125f);

    // 3. softmax rows (fp16 in/out)
    softmax_kernel<<<BATCH * SEQ, 256>>>(scores);

    // 4. attn[b] = probs[b] @ norm1[b]  (B = norm1t) -> fp32
    gemm_f16<0, float><<<dim3(D_MODEL / 128, SEQ / 128, BATCH), 256>>>(
        scores, norm1t, attn, SEQ, D_MODEL, SS, SD, SD, nullptr, nullptr, 1.0f);

    // 5. x = src + attn ; norm2 = LN(x) -> fp16
    add_ln_kernel<<<NTOK, 256>>>(src, attn, gamma2, beta2, x, norm2);

    // 6. h = gelu(norm2 @ w1 + b1)  (B = w1t) -> fp16
    gemm_f16<1, __half><<<dim3(D_FF / 128, NTOK / 128, 1), 256>>>(
        norm2, w1t, h, D_MODEL, D_FF, 0, 0, 0, b1, nullptr, 1.0f);

    // 7. out = h @ w2 + b2 + x  (B = w2t) -> fp32
    gemm_f16<2, float><<<dim3(D_MODEL / 128, NTOK / 128, 1), 256>>>(
        h, w2t, out, D_FF, D_MODEL, 0, 0, 0, b2, x, 1.0f);

    (void)in_sizes; (void)n_in; (void)out_size;
}

// round 13
// speedup vs baseline: 1.0745x; 1.0745x over previous
#include <cuda_runtime.h>
#include <cuda_fp16.h>
#include <math.h>
#include <stdint.h>

#define D_MODEL 1024
#define D_FF    4096
#define BATCH   4
#define SEQ     2048
#define NTOK    (BATCH * SEQ)   // 8192

// ---------------- scratch (allocation-free: __device__ globals) ----------------
__device__ __half g_norm1[(size_t)NTOK * D_MODEL];
__device__ __half g_norm1t[(size_t)NTOK * D_MODEL];      // per-batch [D][S]
__device__ __half g_scores[(size_t)BATCH * SEQ * SEQ];   // scores then probs
__device__ float  g_attn[(size_t)NTOK * D_MODEL];
__device__ float  g_x[(size_t)NTOK * D_MODEL];
__device__ __half g_norm2[(size_t)NTOK * D_MODEL];
__device__ __half g_h[(size_t)NTOK * D_FF];
__device__ __half g_w1t[(size_t)D_FF * D_MODEL];         // [ff][d]
__device__ __half g_w2t[(size_t)D_MODEL * D_FF];         // [d][ff]

// ---------------- reductions ----------------
__device__ __forceinline__ float block_sum(float v, float* sh) {
    int lane = threadIdx.x & 31, w = threadIdx.x >> 5;
    #pragma unroll
    for (int o = 16; o; o >>= 1) v += __shfl_down_sync(0xffffffffu, v, o);
    if (lane == 0) sh[w] = v;
    __syncthreads();
    if (w == 0) {
        float t = (lane < 8) ? sh[lane] : 0.f;
        #pragma unroll
        for (int o = 4; o; o >>= 1) t += __shfl_down_sync(0xffffffffu, t, o);
        if (lane == 0) sh[0] = t;
    }
    __syncthreads();
    float r = sh[0];
    __syncthreads();
    return r;
}

__device__ __forceinline__ float block_max(float v, float* sh) {
    int lane = threadIdx.x & 31, w = threadIdx.x >> 5;
    #pragma unroll
    for (int o = 16; o; o >>= 1) v = fmaxf(v, __shfl_down_sync(0xffffffffu, v, o));
    if (lane == 0) sh[w] = v;
    __syncthreads();
    if (w == 0) {
        float t = (lane < 8) ? sh[lane] : -3.4e38f;
        #pragma unroll
        for (int o = 4; o; o >>= 1) t = fmaxf(t, __shfl_down_sync(0xffffffffu, t, o));
        if (lane == 0) sh[0] = t;
    }
    __syncthreads();
    float r = sh[0];
    __syncthreads();
    return r;
}

// ---------------- LayerNorm (fp16 out) ----------------
__global__ __launch_bounds__(256) void ln_kernel(
    const float* __restrict__ in, const float* __restrict__ gamma,
    const float* __restrict__ beta, __half* __restrict__ out)
{
    __shared__ float sh[32];
    size_t row = blockIdx.x;
    const float* x = in + row * D_MODEL;
    float v[4], s = 0.f;
    #pragma unroll
    for (int i = 0; i < 4; i++) { v[i] = x[threadIdx.x + i * 256]; s += v[i]; }
    float mean = block_sum(s, sh) * (1.0f / D_MODEL);
    float q = 0.f;
    #pragma unroll
    for (int i = 0; i < 4; i++) { float d = v[i] - mean; q += d * d; }
    float var = block_sum(q, sh) * (1.0f / D_MODEL);
    float rstd = rsqrtf(var + 1e-5f);
    __half* y = out + row * D_MODEL;
    #pragma unroll
    for (int i = 0; i < 4; i++) {
        int c = threadIdx.x + i * 256;
        y[c] = __float2half_rn((v[i] - mean) * rstd * gamma[c] + beta[c]);
    }
}

// x fp32; norm2 fp16
__global__ __launch_bounds__(256) void add_ln_kernel(
    const float* __restrict__ src, const float* __restrict__ attn,
    const float* __restrict__ gamma, const float* __restrict__ beta,
    float* __restrict__ xout, __half* __restrict__ nout)
{
    __shared__ float sh[32];
    size_t row = blockIdx.x;
    const float* a = src + row * D_MODEL;
    const float* b = attn + row * D_MODEL;
    float v[4], s = 0.f;
    #pragma unroll
    for (int i = 0; i < 4; i++) {
        int c = threadIdx.x + i * 256;
        v[i] = a[c] + b[c];
        s += v[i];
    }
    float* xo = xout + row * D_MODEL;
    #pragma unroll
    for (int i = 0; i < 4; i++) xo[threadIdx.x + i * 256] = v[i];
    float mean = block_sum(s, sh) * (1.0f / D_MODEL);
    float q = 0.f;
    #pragma unroll
    for (int i = 0; i < 4; i++) { float d = v[i] - mean; q += d * d; }
    float var = block_sum(q, sh) * (1.0f / D_MODEL);
    float rstd = rsqrtf(var + 1e-5f);
    __half* y = nout + row * D_MODEL;
    #pragma unroll
    for (int i = 0; i < 4; i++) {
        int c = threadIdx.x + i * 256;
        y[c] = __float2half_rn((v[i] - mean) * rstd * gamma[c] + beta[c]);
    }
}

// ---------------- softmax over fp16 rows of length SEQ (in place) ----------------
__global__ __launch_bounds__(256) void softmax_kernel(__half* __restrict__ sc)
{
    __shared__ float sh[32];
    size_t row = blockIdx.x;
    __half* p = sc + row * (size_t)SEQ;
    float v[8], m = -3.4e38f;
    #pragma unroll
    for (int i = 0; i < 8; i++) { v[i] = __half2float(p[threadIdx.x + i * 256]); m = fmaxf(m, v[i]); }
    m = block_max(m, sh);
    float s = 0.f;
    #pragma unroll
    for (int i = 0; i < 8; i++) { v[i] = __expf(v[i] - m); s += v[i]; }
    s = block_sum(s, sh);
    float inv = 1.0f / s;
    #pragma unroll
    for (int i = 0; i < 8; i++) p[threadIdx.x + i * 256] = __float2half_rn(v[i] * inv);
}

// ---------------- tiled transpose + convert: out[C][R] = cvt(in[R][C])^T ------
template<typename TIN>
__global__ __launch_bounds__(256) void transpose_cvt(
    const TIN* __restrict__ in, __half* __restrict__ out,
    int R, int C, size_t sI, size_t sO)
{
    in += blockIdx.z * sI; out += blockIdx.z * sO;
    __shared__ float t[32][33];
    int tx = threadIdx.x & 31, ty = threadIdx.x >> 5;
    int c = blockIdx.x * 32 + tx;
    int r0 = blockIdx.y * 32;
    #pragma unroll
    for (int i = 0; i < 4; i++)
        t[ty + i * 8][tx] = (float)in[(size_t)(r0 + ty + i * 8) * C + c];
    __syncthreads();
    int rc = r0 + tx;
    int oc0 = blockIdx.x * 32;
    #pragma unroll
    for (int i = 0; i < 4; i++)
        out[(size_t)(oc0 + ty + i * 8) * R + rc] = __float2half_rn(t[tx][ty + i * 8]);
}

// ======================= FP16 HMMA GEMM (NT, ldmatrix, BK=32) =================
// C[M,N] = A[M,K] @ Bt[N,K]^T, operands fp16, accumulate fp32.
// Block 128x128, 128 threads = 4 warps 2x2, warp tile 64x64,
// mma.sync.m16n8k16, BK=32 double-buffered, smem row stride 20 words:
//   LDSM phase banks 20r%32 distinct; STS.128 phase units 5t%8 distinct -> CF.
// All 16 LDSM for the chunk are issued up front, then 64 back-to-back MMAs.
// EPI: 0 = scale*AB -> TOUT   1 = gelu(AB+bias) -> half   2 = AB+bias+resid -> float

__device__ __forceinline__ uint32_t smem_u32(const void* p) {
    uint32_t a;
    asm("{ .reg .u64 t; cvta.to.shared.u64 t, %1; cvt.u32.u64 %0, t; }" : "=r"(a) : "l"(p));
    return a;
}

__device__ __forceinline__ void ldsm4(uint32_t& r0, uint32_t& r1, uint32_t& r2, uint32_t& r3,
                                      uint32_t addr) {
    asm volatile("ldmatrix.sync.aligned.m8n8.x4.shared.b16 {%0,%1,%2,%3}, [%4];"
                 : "=r"(r0), "=r"(r1), "=r"(r2), "=r"(r3) : "r"(addr));
}

__device__ __forceinline__ void mma16(float* c, const uint32_t* a, const uint32_t* b) {
    asm volatile(
        "mma.sync.aligned.m16n8k16.row.col.f32.f16.f16.f32 "
        "{%0,%1,%2,%3}, {%4,%5,%6,%7}, {%8,%9}, {%0,%1,%2,%3};"
        : "+f"(c[0]), "+f"(c[1]), "+f"(c[2]), "+f"(c[3])
        : "r"(a[0]), "r"(a[1]), "r"(a[2]), "r"(a[3]), "r"(b[0]), "r"(b[1]));
}

__device__ __forceinline__ float gelu_exact(float v) {
    return v * 0.5f * (1.0f + erff(v * 0.70710678118654752f));
}

__device__ __forceinline__ void store2(__half* p, float a, float b) {
    *(__half2*)p = __floats2half2_rn(a, b);
}
__device__ __forceinline__ void store2(float* p, float a, float b) {
    p[0] = a; p[1] = b;
}

#define RSTR 20                       // smem row stride in 32-bit words
#define TILEW (128 * RSTR)            // words per tile buffer
#define TILEBYTES (TILEW * 4)         // 10240

template<int EPI, typename TOUT>
__global__ __launch_bounds__(128, 2) void gemm_f16(
    const __half* __restrict__ A, const __half* __restrict__ Bt, TOUT* __restrict__ C,
    int K, int N, size_t sA, size_t sB, size_t sC,
    const float* __restrict__ bias, const float* __restrict__ resid, float scale)
{
    A += blockIdx.z * sA; Bt += blockIdx.z * sB; C += blockIdx.z * sC;
    if (EPI == 2) resid += blockIdx.z * sC;

    __shared__ uint32_t As[2][TILEW];
    __shared__ uint32_t Bs[2][TILEW];

    const int tid  = threadIdx.x;
    const int lane = tid & 31;
    const int warp = tid >> 5;
    const int warpM = warp >> 1;   // 0..1
    const int warpN = warp & 1;    // 0..1
    const int r  = lane >> 2;      // 0..7
    const int cq = lane & 3;       // 0..3

    const int row0 = blockIdx.y * 128;
    const int col0 = blockIdx.x * 128;

    const __half* pa = A + (size_t)(row0 + tid) * K;
    const __half* pb = Bt + (size_t)(col0 + tid) * K;

    // ldmatrix lane addresses (buffer 0, sub-chunk 0)
    const uint32_t asBase = smem_u32(As);
    const uint32_t bsBase = smem_u32(Bs);
    uint32_t aAddr[4], bAddr[4];
    {
        int mrow = (lane & 7) + ((lane >> 3) & 1) * 8;   // row within 16
        int seg  = lane >> 4;                            // k segment 0/1
        #pragma unroll
        for (int i = 0; i < 4; i++) {
            int m = warpM * 64 + i * 16 + mrow;
            aAddr[i] = asBase + (uint32_t)(m * RSTR + seg * 4) * 4;
        }
        int nrow = (lane & 7) + ((lane >> 4) & 1) * 8;   // row within 16 (two j's)
        int bseg = (lane >> 3) & 1;
        #pragma unroll
        for (int jp = 0; jp < 4; jp++) {
            int n = warpN * 64 + jp * 16 + nrow;
            bAddr[jp] = bsBase + (uint32_t)(n * RSTR + bseg * 4) * 4;
        }
    }

    float acc[4][8][4] = {};
    uint4 ra[4], rb[4];

    auto ldg_tile = [&](int c) {
        const uint4* qa = (const uint4*)(pa + c * 32);
        const uint4* qb = (const uint4*)(pb + c * 32);
        #pragma unroll
        for (int i = 0; i < 4; i++) { ra[i] = qa[i]; rb[i] = qb[i]; }
    };
    auto sts_tile = [&](int nb) {
        #pragma unroll
        for (int i = 0; i < 4; i++) {
            *(uint4*)&As[nb][tid * RSTR + i * 4] = ra[i];
            *(uint4*)&Bs[nb][tid * RSTR + i * 4] = rb[i];
        }
    };

    ldg_tile(0);
    sts_tile(0);
    __syncthreads();

    const int nch = K / 32;
    int buf = 0;
    for (int c = 0; c < nch; c++) {
        const bool more = (c + 1 < nch);
        if (more) ldg_tile(c + 1);

        const uint32_t bo = (uint32_t)buf * TILEBYTES;
        // ---- all fragment loads for the chunk up front ----
        uint32_t af[2][4][4], bf[2][8][2];
        #pragma unroll
        for (int s = 0; s < 2; s++) {
            const uint32_t so = bo + (uint32_t)s * 32;   // +8 words per sub-chunk
            #pragma unroll
            for (int i = 0; i < 4; i++)
                ldsm4(af[s][i][0], af[s][i][1], af[s][i][2], af[s][i][3], aAddr[i] + so);
            #pragma unroll
            for (int jp = 0; jp < 4; jp++)
                ldsm4(bf[s][2 * jp][0], bf[s][2 * jp][1],
                      bf[s][2 * jp + 1][0], bf[s][2 * jp + 1][1], bAddr[jp] + so);
        }
        // ---- 64 back-to-back MMAs ----
        #pragma unroll
        for (int s = 0; s < 2; s++)
            #pragma unroll
            for (int i = 0; i < 4; i++)
                #pragma unroll
                for (int j = 0; j < 8; j++)
                    mma16(acc[i][j], af[s][i], bf[s][j]);

        if (more) {
            sts_tile(buf ^ 1);
            __syncthreads();
            buf ^= 1;
        }
    }

    // ---- epilogue ----
    #pragma unroll
    for (int i = 0; i < 4; i++) {
        int mrow = row0 + warpM * 64 + i * 16 + r;
        #pragma unroll
        for (int j = 0; j < 8; j++) {
            int ncol = col0 + warpN * 64 + j * 8 + 2 * cq;
            float v0 = acc[i][j][0], v1 = acc[i][j][1];
            float v2 = acc[i][j][2], v3 = acc[i][j][3];
            size_t p0 = (size_t)mrow * N + ncol;
            size_t p1 = (size_t)(mrow + 8) * N + ncol;
            if (EPI == 0) {
                v0 *= scale; v1 *= scale; v2 *= scale; v3 *= scale;
            } else {
                float bb0 = bias[ncol], bb1 = bias[ncol + 1];
                if (EPI == 1) {
                    v0 = gelu_exact(v0 + bb0); v1 = gelu_exact(v1 + bb1);
                    v2 = gelu_exact(v2 + bb0); v3 = gelu_exact(v3 + bb1);
                } else {
                    v0 += bb0 + resid[p0];     v1 += bb1 + resid[p0 + 1];
                    v2 += bb0 + resid[p1];     v3 += bb1 + resid[p1 + 1];
                }
            }
            store2(C + p0, v0, v1);
            store2(C + p1, v2, v3);
        }
    }
}

// ---------------- launch ----------------
extern "C" void kernel_launch(void* const* d_in, const int* in_sizes, int n_in,
                              void* d_out, int out_size)
{
    const float* src    = (const float*)d_in[0];
    const float* gamma1 = (const float*)d_in[1];
    const float* beta1  = (const float*)d_in[2];
    const float* gamma2 = (const float*)d_in[3];
    const float* beta2  = (const float*)d_in[4];
    const float* w1     = (const float*)d_in[5];
    const float* b1     = (const float*)d_in[6];
    const float* w2     = (const float*)d_in[7];
    const float* b2     = (const float*)d_in[8];
    float* out = (float*)d_out;

    __half *norm1, *norm1t, *scores, *norm2, *h, *w1t, *w2t;
    float *attn, *x;
    cudaGetSymbolAddress((void**)&norm1, g_norm1);
    cudaGetSymbolAddress((void**)&norm1t, g_norm1t);
    cudaGetSymbolAddress((void**)&scores, g_scores);
    cudaGetSymbolAddress((void**)&attn, g_attn);
    cudaGetSymbolAddress((void**)&x, g_x);
    cudaGetSymbolAddress((void**)&norm2, g_norm2);
    cudaGetSymbolAddress((void**)&h, g_h);
    cudaGetSymbolAddress((void**)&w1t, g_w1t);
    cudaGetSymbolAddress((void**)&w2t, g_w2t);

    const size_t SD = (size_t)SEQ * D_MODEL;
    const size_t SS = (size_t)SEQ * SEQ;

    // 0. weight transpose + fp16 convert: w1t[ff][d], w2t[d][ff]
    transpose_cvt<float><<<dim3(D_FF / 32, D_MODEL / 32, 1), 256>>>(w1, w1t, D_MODEL, D_FF, 0, 0);
    transpose_cvt<float><<<dim3(D_MODEL / 32, D_FF / 32, 1), 256>>>(w2, w2t, D_FF, D_MODEL, 0, 0);

    // 1. norm1 = LN(src) -> fp16
    ln_kernel<<<NTOK, 256>>>(src, gamma1, beta1, norm1);

    // 1b. norm1t[b] = norm1[b]^T  ([D][S] per batch, fp16)
    transpose_cvt<__half><<<dim3(D_MODEL / 32, SEQ / 32, BATCH), 256>>>(
        norm1, norm1t, SEQ, D_MODEL, SD, SD);

    // 2. scores[b] = norm1[b] @ norm1[b]^T / 32  -> fp16
    gemm_f16<0, __half><<<dim3(SEQ / 128, SEQ / 128, BATCH), 128>>>(
        norm1, norm1, scores, D_MODEL, SEQ, SD, SD, SS, nullptr, nullptr, 0.03125f);

    // 3. softmax rows (fp16 in/out)
    softmax_kernel<<<BATCH * SEQ, 256>>>(scores);

    // 4. attn[b] = probs[b] @ norm1[b]  (B = norm1t) -> fp32
    gemm_f16<0, float><<<dim3(D_MODEL / 128, SEQ / 128, BATCH), 128>>>(
        scores, norm1t, attn, SEQ, D_MODEL, SS, SD, SD, nullptr, nullptr, 1.0f);

    // 5. x = src + attn ; norm2 = LN(x) -> fp16
    add_ln_kernel<<<NTOK, 256>>>(src, attn, gamma2, beta2, x, norm2);

    // 6. h = gelu(norm2 @ w1 + b1)  (B = w1t) -> fp16
    gemm_f16<1, __half><<<dim3(D_FF / 128, NTOK / 128, 1), 128>>>(
        norm2, w1t, h, D_MODEL, D_FF, 0, 0, 0, b1, nullptr, 1.0f);

    // 7. out = h @ w2 + b2 + x  (B = w2t) -> fp32
    gemm_f16<2, float><<<dim3(D_MODEL / 128, NTOK / 128, 1), 128>>>(
        h, w2t, out, D_FF, D_MODEL, 0, 0, 0, b2, x, 1.0f);

    (void)in_sizes; (void)n_in; (void)out_size;
}

// round 14
// speedup vs baseline: 1.1372x; 1.0583x over previous
#include <cuda_runtime.h>
#include <cuda_fp16.h>
#include <math.h>
#include <stdint.h>

#define D_MODEL 1024
#define D_FF    4096
#define BATCH   4
#define SEQ     2048
#define NTOK    (BATCH * SEQ)   // 8192

// ---------------- scratch (allocation-free: __device__ globals) ----------------
__device__ __half g_norm1[(size_t)NTOK * D_MODEL];
__device__ __half g_norm1t[(size_t)NTOK * D_MODEL];      // per-batch [D][S]
__device__ __half g_scores[(size_t)BATCH * SEQ * SEQ];   // scores then probs
__device__ float  g_attn[(size_t)NTOK * D_MODEL];
__device__ float  g_x[(size_t)NTOK * D_MODEL];
__device__ __half g_norm2[(size_t)NTOK * D_MODEL];
__device__ __half g_h[(size_t)NTOK * D_FF];
__device__ __half g_w1t[(size_t)D_FF * D_MODEL];         // [ff][d]
__device__ __half g_w2t[(size_t)D_MODEL * D_FF];         // [d][ff]

// ---------------- reductions ----------------
__device__ __forceinline__ float block_sum(float v, float* sh) {
    int lane = threadIdx.x & 31, w = threadIdx.x >> 5;
    #pragma unroll
    for (int o = 16; o; o >>= 1) v += __shfl_down_sync(0xffffffffu, v, o);
    if (lane == 0) sh[w] = v;
    __syncthreads();
    if (w == 0) {
        float t = (lane < 8) ? sh[lane] : 0.f;
        #pragma unroll
        for (int o = 4; o; o >>= 1) t += __shfl_down_sync(0xffffffffu, t, o);
        if (lane == 0) sh[0] = t;
    }
    __syncthreads();
    float r = sh[0];
    __syncthreads();
    return r;
}

__device__ __forceinline__ float block_max(float v, float* sh) {
    int lane = threadIdx.x & 31, w = threadIdx.x >> 5;
    #pragma unroll
    for (int o = 16; o; o >>= 1) v = fmaxf(v, __shfl_down_sync(0xffffffffu, v, o));
    if (lane == 0) sh[w] = v;
    __syncthreads();
    if (w == 0) {
        float t = (lane < 8) ? sh[lane] : -3.4e38f;
        #pragma unroll
        for (int o = 4; o; o >>= 1) t = fmaxf(t, __shfl_down_sync(0xffffffffu, t, o));
        if (lane == 0) sh[0] = t;
    }
    __syncthreads();
    float r = sh[0];
    __syncthreads();
    return r;
}

// ---------------- LayerNorm (fp16 out) ----------------
__global__ __launch_bounds__(256) void ln_kernel(
    const float* __restrict__ in, const float* __restrict__ gamma,
    const float* __restrict__ beta, __half* __restrict__ out)
{
    __shared__ float sh[32];
    size_t row = blockIdx.x;
    const float* x = in + row * D_MODEL;
    float v[4], s = 0.f;
    #pragma unroll
    for (int i = 0; i < 4; i++) { v[i] = x[threadIdx.x + i * 256]; s += v[i]; }
    float mean = block_sum(s, sh) * (1.0f / D_MODEL);
    float q = 0.f;
    #pragma unroll
    for (int i = 0; i < 4; i++) { float d = v[i] - mean; q += d * d; }
    float var = block_sum(q, sh) * (1.0f / D_MODEL);
    float rstd = rsqrtf(var + 1e-5f);
    __half* y = out + row * D_MODEL;
    #pragma unroll
    for (int i = 0; i < 4; i++) {
        int c = threadIdx.x + i * 256;
        y[c] = __float2half_rn((v[i] - mean) * rstd * gamma[c] + beta[c]);
    }
}

// x fp32; norm2 fp16
__global__ __launch_bounds__(256) void add_ln_kernel(
    const float* __restrict__ src, const float* __restrict__ attn,
    const float* __restrict__ gamma, const float* __restrict__ beta,
    float* __restrict__ xout, __half* __restrict__ nout)
{
    __shared__ float sh[32];
    size_t row = blockIdx.x;
    const float* a = src + row * D_MODEL;
    const float* b = attn + row * D_MODEL;
    float v[4], s = 0.f;
    #pragma unroll
    for (int i = 0; i < 4; i++) {
        int c = threadIdx.x + i * 256;
        v[i] = a[c] + b[c];
        s += v[i];
    }
    float* xo = xout + row * D_MODEL;
    #pragma unroll
    for (int i = 0; i < 4; i++) xo[threadIdx.x + i * 256] = v[i];
    float mean = block_sum(s, sh) * (1.0f / D_MODEL);
    float q = 0.f;
    #pragma unroll
    for (int i = 0; i < 4; i++) { float d = v[i] - mean; q += d * d; }
    float var = block_sum(q, sh) * (1.0f / D_MODEL);
    float rstd = rsqrtf(var + 1e-5f);
    __half* y = nout + row * D_MODEL;
    #pragma unroll
    for (int i = 0; i < 4; i++) {
        int c = threadIdx.x + i * 256;
        y[c] = __float2half_rn((v[i] - mean) * rstd * gamma[c] + beta[c]);
    }
}

// ---------------- softmax over fp16 rows (in place, vectorized uint4) --------
__global__ __launch_bounds__(256) void softmax_kernel(__half* __restrict__ sc)
{
    __shared__ float sh[32];
    size_t row = blockIdx.x;
    __half* p = sc + row * (size_t)SEQ;
    uint4 u = ((const uint4*)p)[threadIdx.x];
    __half2* hp = (__half2*)&u;
    float v[8], m = -3.4e38f;
    #pragma unroll
    for (int i = 0; i < 4; i++) {
        float2 f = __half22float2(hp[i]);
        v[2 * i] = f.x; v[2 * i + 1] = f.y;
        m = fmaxf(m, fmaxf(f.x, f.y));
    }
    m = block_max(m, sh);
    float s = 0.f;
    #pragma unroll
    for (int i = 0; i < 8; i++) { v[i] = __expf(v[i] - m); s += v[i]; }
    s = block_sum(s, sh);
    float inv = 1.0f / s;
    #pragma unroll
    for (int i = 0; i < 4; i++)
        hp[i] = __floats2half2_rn(v[2 * i] * inv, v[2 * i + 1] * inv);
    ((uint4*)p)[threadIdx.x] = u;
}

// ---------------- mirror upper-triangular 128-blocks to lower ----------------
// scores[r][c] = scores[c][r] for 128-block row > 128-block col (bitwise exact).
__global__ __launch_bounds__(256) void mirror_kernel(__half* __restrict__ sc)
{
    if ((blockIdx.y >> 2) <= (blockIdx.x >> 2)) return;   // only strict lower 128-blocks
    __half* p = sc + blockIdx.z * (size_t)SEQ * SEQ;
    __shared__ __half t[32][33];
    int tx = threadIdx.x & 31, ty = threadIdx.x >> 5;
    int R0 = blockIdx.y * 32, C0 = blockIdx.x * 32;       // output tile
    #pragma unroll
    for (int i = 0; i < 4; i++)                            // read source (upper) tile
        t[ty + i * 8][tx] = p[(size_t)(C0 + ty + i * 8) * SEQ + R0 + tx];
    __syncthreads();
    #pragma unroll
    for (int i = 0; i < 4; i++)
        p[(size_t)(R0 + ty + i * 8) * SEQ + C0 + tx] = t[tx][ty + i * 8];
}

// ---------------- tiled transpose + convert: out[C][R] = cvt(in[R][C])^T ------
template<typename TIN>
__global__ __launch_bounds__(256) void transpose_cvt(
    const TIN* __restrict__ in, __half* __restrict__ out,
    int R, int C, size_t sI, size_t sO)
{
    in += blockIdx.z * sI; out += blockIdx.z * sO;
    __shared__ float t[32][33];
    int tx = threadIdx.x & 31, ty = threadIdx.x >> 5;
    int c = blockIdx.x * 32 + tx;
    int r0 = blockIdx.y * 32;
    #pragma unroll
    for (int i = 0; i < 4; i++)
        t[ty + i * 8][tx] = (float)in[(size_t)(r0 + ty + i * 8) * C + c];
    __syncthreads();
    int rc = r0 + tx;
    int oc0 = blockIdx.x * 32;
    #pragma unroll
    for (int i = 0; i < 4; i++)
        out[(size_t)(oc0 + ty + i * 8) * R + rc] = __float2half_rn(t[tx][ty + i * 8]);
}

// ======================= FP16 HMMA GEMM (NT, ldmatrix, BK=32) =================
// C[M,N] = A[M,K] @ Bt[N,K]^T, operands fp16, accumulate fp32.
// Block 128x128, 128 threads = 4 warps 2x2, warp tile 64x64,
// mma.sync.m16n8k16, BK=32 double-buffered, smem row stride 20 words:
//   LDSM phase banks 20r%32 distinct; STS.128 phase units 5t%8 distinct -> CF.
// All 16 LDSM for the chunk are issued up front, then 64 back-to-back MMAs.
// SYMM: skip CTAs with bx<by (caller mirrors afterwards).
// EPI: 0 = scale*AB -> TOUT   1 = gelu(AB+bias) -> half   2 = AB+bias+resid -> float

__device__ __forceinline__ uint32_t smem_u32(const void* p) {
    uint32_t a;
    asm("{ .reg .u64 t; cvta.to.shared.u64 t, %1; cvt.u32.u64 %0, t; }" : "=r"(a) : "l"(p));
    return a;
}

__device__ __forceinline__ void ldsm4(uint32_t& r0, uint32_t& r1, uint32_t& r2, uint32_t& r3,
                                      uint32_t addr) {
    asm volatile("ldmatrix.sync.aligned.m8n8.x4.shared.b16 {%0,%1,%2,%3}, [%4];"
                 : "=r"(r0), "=r"(r1), "=r"(r2), "=r"(r3) : "r"(addr));
}

__device__ __forceinline__ void mma16(float* c, const uint32_t* a, const uint32_t* b) {
    asm volatile(
        "mma.sync.aligned.m16n8k16.row.col.f32.f16.f16.f32 "
        "{%0,%1,%2,%3}, {%4,%5,%6,%7}, {%8,%9}, {%0,%1,%2,%3};"
        : "+f"(c[0]), "+f"(c[1]), "+f"(c[2]), "+f"(c[3])
        : "r"(a[0]), "r"(a[1]), "r"(a[2]), "r"(a[3]), "r"(b[0]), "r"(b[1]));
}

__device__ __forceinline__ float gelu_exact(float v) {
    return v * 0.5f * (1.0f + erff(v * 0.70710678118654752f));
}

__device__ __forceinline__ void store2(__half* p, float a, float b) {
    *(__half2*)p = __floats2half2_rn(a, b);
}
__device__ __forceinline__ void store2(float* p, float a, float b) {
    p[0] = a; p[1] = b;
}

#define RSTR 20                       // smem row stride in 32-bit words
#define TILEW (128 * RSTR)            // words per tile buffer
#define TILEBYTES (TILEW * 4)         // 10240

template<int EPI, int SYMM, typename TOUT>
__global__ __launch_bounds__(128, 2) void gemm_f16(
    const __half* __restrict__ A, const __half* __restrict__ Bt, TOUT* __restrict__ C,
    int K, int N, size_t sA, size_t sB, size_t sC,
    const float* __restrict__ bias, const float* __restrict__ resid, float scale)
{
    if (SYMM && blockIdx.x < blockIdx.y) return;   // lower blocks filled by mirror

    A += blockIdx.z * sA; Bt += blockIdx.z * sB; C += blockIdx.z * sC;
    if (EPI == 2) resid += blockIdx.z * sC;

    __shared__ uint32_t As[2][TILEW];
    __shared__ uint32_t Bs[2][TILEW];

    const int tid  = threadIdx.x;
    const int lane = tid & 31;
    const int warp = tid >> 5;
    const int warpM = warp >> 1;   // 0..1
    const int warpN = warp & 1;    // 0..1
    const int r  = lane >> 2;      // 0..7
    const int cq = lane & 3;       // 0..3

    const int row0 = blockIdx.y * 128;
    const int col0 = blockIdx.x * 128;

    const __half* pa = A + (size_t)(row0 + tid) * K;
    const __half* pb = Bt + (size_t)(col0 + tid) * K;

    // ldmatrix lane addresses (buffer 0, sub-chunk 0)
    const uint32_t asBase = smem_u32(As);
    const uint32_t bsBase = smem_u32(Bs);
    uint32_t aAddr[4], bAddr[4];
    {
        int mrow = (lane & 7) + ((lane >> 3) & 1) * 8;   // row within 16
        int seg  = lane >> 4;                            // k segment 0/1
        #pragma unroll
        for (int i = 0; i < 4; i++) {
            int m = warpM * 64 + i * 16 + mrow;
            aAddr[i] = asBase + (uint32_t)(m * RSTR + seg * 4) * 4;
        }
        int nrow = (lane & 7) + ((lane >> 4) & 1) * 8;   // row within 16 (two j's)
        int bseg = (lane >> 3) & 1;
        #pragma unroll
        for (int jp = 0; jp < 4; jp++) {
            int n = warpN * 64 + jp * 16 + nrow;
            bAddr[jp] = bsBase + (uint32_t)(n * RSTR + bseg * 4) * 4;
        }
    }

    float acc[4][8][4] = {};
    uint4 ra[4], rb[4];

    auto ldg_tile = [&](int c) {
        const uint4* qa = (const uint4*)(pa + c * 32);
        const uint4* qb = (const uint4*)(pb + c * 32);
        #pragma unroll
        for (int i = 0; i < 4; i++) { ra[i] = qa[i]; rb[i] = qb[i]; }
    };
    auto sts_tile = [&](int nb) {
        #pragma unroll
        for (int i = 0; i < 4; i++) {
            *(uint4*)&As[nb][tid * RSTR + i * 4] = ra[i];
            *(uint4*)&Bs[nb][tid * RSTR + i * 4] = rb[i];
        }
    };

    ldg_tile(0);
    sts_tile(0);
    __syncthreads();

    const int nch = K / 32;
    int buf = 0;
    for (int c = 0; c < nch; c++) {
        const bool more = (c + 1 < nch);
        if (more) ldg_tile(c + 1);

        const uint32_t bo = (uint32_t)buf * TILEBYTES;
        // ---- all fragment loads for the chunk up front ----
        uint32_t af[2][4][4], bf[2][8][2];
        #pragma unroll
        for (int s = 0; s < 2; s++) {
            const uint32_t so = bo + (uint32_t)s * 32;   // +8 words per sub-chunk
            #pragma unroll
            for (int i = 0; i < 4; i++)
                ldsm4(af[s][i][0], af[s][i][1], af[s][i][2], af[s][i][3], aAddr[i] + so);
            #pragma unroll
            for (int jp = 0; jp < 4; jp++)
                ldsm4(bf[s][2 * jp][0], bf[s][2 * jp][1],
                      bf[s][2 * jp + 1][0], bf[s][2 * jp + 1][1], bAddr[jp] + so);
        }
        // ---- 64 back-to-back MMAs ----
        #pragma unroll
        for (int s = 0; s < 2; s++)
            #pragma unroll
            for (int i = 0; i < 4; i++)
                #pragma unroll
                for (int j = 0; j < 8; j++)
                    mma16(acc[i][j], af[s][i], bf[s][j]);

        if (more) {
            sts_tile(buf ^ 1);
            __syncthreads();
            buf ^= 1;
        }
    }

    // ---- epilogue ----
    #pragma unroll
    for (int i = 0; i < 4; i++) {
        int mrow = row0 + warpM * 64 + i * 16 + r;
        #pragma unroll
        for (int j = 0; j < 8; j++) {
            int ncol = col0 + warpN * 64 + j * 8 + 2 * cq;
            float v0 = acc[i][j][0], v1 = acc[i][j][1];
            float v2 = acc[i][j][2], v3 = acc[i][j][3];
            size_t p0 = (size_t)mrow * N + ncol;
            size_t p1 = (size_t)(mrow + 8) * N + ncol;
            if (EPI == 0) {
                v0 *= scale; v1 *= scale; v2 *= scale; v3 *= scale;
            } else {
                float bb0 = bias[ncol], bb1 = bias[ncol + 1];
                if (EPI == 1) {
                    v0 = gelu_exact(v0 + bb0); v1 = gelu_exact(v1 + bb1);
                    v2 = gelu_exact(v2 + bb0); v3 = gelu_exact(v3 + bb1);
                } else {
                    v0 += bb0 + resid[p0];     v1 += bb1 + resid[p0 + 1];
                    v2 += bb0 + resid[p1];     v3 += bb1 + resid[p1 + 1];
                }
            }
            store2(C + p0, v0, v1);
            store2(C + p1, v2, v3);
        }
    }
}

// ---------------- launch ----------------
extern "C" void kernel_launch(void* const* d_in, const int* in_sizes, int n_in,
                              void* d_out, int out_size)
{
    const float* src    = (const float*)d_in[0];
    const float* gamma1 = (const float*)d_in[1];
    const float* beta1  = (const float*)d_in[2];
    const float* gamma2 = (const float*)d_in[3];
    const float* beta2  = (const float*)d_in[4];
    const float* w1     = (const float*)d_in[5];
    const float* b1     = (const float*)d_in[6];
    const float* w2     = (const float*)d_in[7];
    const float* b2     = (const float*)d_in[8];
    float* out = (float*)d_out;

    __half *norm1, *norm1t, *scores, *norm2, *h, *w1t, *w2t;
    float *attn, *x;
    cudaGetSymbolAddress((void**)&norm1, g_norm1);
    cudaGetSymbolAddress((void**)&norm1t, g_norm1t);
    cudaGetSymbolAddress((void**)&scores, g_scores);
    cudaGetSymbolAddress((void**)&attn, g_attn);
    cudaGetSymbolAddress((void**)&x, g_x);
    cudaGetSymbolAddress((void**)&norm2, g_norm2);
    cudaGetSymbolAddress((void**)&h, g_h);
    cudaGetSymbolAddress((void**)&w1t, g_w1t);
    cudaGetSymbolAddress((void**)&w2t, g_w2t);

    const size_t SD = (size_t)SEQ * D_MODEL;
    const size_t SS = (size_t)SEQ * SEQ;

    // 0. weight transpose + fp16 convert: w1t[ff][d], w2t[d][ff]
    transpose_cvt<float><<<dim3(D_FF / 32, D_MODEL / 32, 1), 256>>>(w1, w1t, D_MODEL, D_FF, 0, 0);
    transpose_cvt<float><<<dim3(D_MODEL / 32, D_FF / 32, 1), 256>>>(w2, w2t, D_FF, D_MODEL, 0, 0);

    // 1. norm1 = LN(src) -> fp16
    ln_kernel<<<NTOK, 256>>>(src, gamma1, beta1, norm1);

    // 1b. norm1t[b] = norm1[b]^T  ([D][S] per batch, fp16)
    transpose_cvt<__half><<<dim3(D_MODEL / 32, SEQ / 32, BATCH), 256>>>(
        norm1, norm1t, SEQ, D_MODEL, SD, SD);

    // 2. scores[b] = norm1[b] @ norm1[b]^T / 32  -> fp16, upper blocks only
    gemm_f16<0, 1, __half><<<dim3(SEQ / 128, SEQ / 128, BATCH), 128>>>(
        norm1, norm1, scores, D_MODEL, SEQ, SD, SD, SS, nullptr, nullptr, 0.03125f);

    // 2b. mirror to lower blocks (bitwise exact)
    mirror_kernel<<<dim3(SEQ / 32, SEQ / 32, BATCH), 256>>>(scores);

    // 3. softmax rows (fp16 in/out, vectorized)
    softmax_kernel<<<BATCH * SEQ, 256>>>(scores);

    // 4. attn[b] = probs[b] @ norm1[b]  (B = norm1t) -> fp32
    gemm_f16<0, 0, float><<<dim3(D_MODEL / 128, SEQ / 128, BATCH), 128>>>(
        scores, norm1t, attn, SEQ, D_MODEL, SS, SD, SD, nullptr, nullptr, 1.0f);

    // 5. x = src + attn ; norm2 = LN(x) -> fp16
    add_ln_kernel<<<NTOK, 256>>>(src, attn, gamma2, beta2, x, norm2);

    // 6. h = gelu(norm2 @ w1 + b1)  (B = w1t) -> fp16
    gemm_f16<1, 0, __half><<<dim3(D_FF / 128, NTOK / 128, 1), 128>>>(
        norm2, w1t, h, D_MODEL, D_FF, 0, 0, 0, b1, nullptr, 1.0f);

    // 7. out = h @ w2 + b2 + x  (B = w2t) -> fp32
    gemm_f16<2, 0, float><<<dim3(D_MODEL / 128, NTOK / 128, 1), 128>>>(
        h, w2t, out, D_FF, D_MODEL, 0, 0, 0, b2, x, 1.0f);

    (void)in_sizes; (void)n_in; (void)out_size;
}

// round 15
// speedup vs baseline: 1.1501x; 1.0114x over previous
#include <cuda_runtime.h>
#include <cuda_fp16.h>
#include <math.h>
#include <stdint.h>

#define D_MODEL 1024
#define D_FF    4096
#define BATCH   4
#define SEQ     2048
#define NTOK    (BATCH * SEQ)   // 8192

// ---------------- scratch (allocation-free: __device__ globals) ----------------
__device__ __half g_norm1[(size_t)NTOK * D_MODEL];
__device__ __half g_norm1t[(size_t)NTOK * D_MODEL];      // per-batch [D][S]
__device__ __half g_scores[(size_t)BATCH * SEQ * SEQ];   // scores then probs
__device__ float  g_x[(size_t)NTOK * D_MODEL];
__device__ __half g_norm2[(size_t)NTOK * D_MODEL];
__device__ __half g_h[(size_t)NTOK * D_FF];
__device__ __half g_w1t[(size_t)D_FF * D_MODEL];         // [ff][d]
__device__ __half g_w2t[(size_t)D_MODEL * D_FF];         // [d][ff]

// ---------------- reductions ----------------
__device__ __forceinline__ float block_sum(float v, float* sh) {
    int lane = threadIdx.x & 31, w = threadIdx.x >> 5;
    #pragma unroll
    for (int o = 16; o; o >>= 1) v += __shfl_down_sync(0xffffffffu, v, o);
    if (lane == 0) sh[w] = v;
    __syncthreads();
    if (w == 0) {
        float t = (lane < 8) ? sh[lane] : 0.f;
        #pragma unroll
        for (int o = 4; o; o >>= 1) t += __shfl_down_sync(0xffffffffu, t, o);
        if (lane == 0) sh[0] = t;
    }
    __syncthreads();
    float r = sh[0];
    __syncthreads();
    return r;
}

__device__ __forceinline__ float block_max(float v, float* sh) {
    int lane = threadIdx.x & 31, w = threadIdx.x >> 5;
    #pragma unroll
    for (int o = 16; o; o >>= 1) v = fmaxf(v, __shfl_down_sync(0xffffffffu, v, o));
    if (lane == 0) sh[w] = v;
    __syncthreads();
    if (w == 0) {
        float t = (lane < 8) ? sh[lane] : -3.4e38f;
        #pragma unroll
        for (int o = 4; o; o >>= 1) t = fmaxf(t, __shfl_down_sync(0xffffffffu, t, o));
        if (lane == 0) sh[0] = t;
    }
    __syncthreads();
    float r = sh[0];
    __syncthreads();
    return r;
}

// ---------------- LayerNorm (fp32 in, fp16 out) ----------------
__global__ __launch_bounds__(256) void ln_kernel(
    const float* __restrict__ in, const float* __restrict__ gamma,
    const float* __restrict__ beta, __half* __restrict__ out)
{
    __shared__ float sh[32];
    size_t row = blockIdx.x;
    const float* x = in + row * D_MODEL;
    float v[4], s = 0.f;
    #pragma unroll
    for (int i = 0; i < 4; i++) { v[i] = x[threadIdx.x + i * 256]; s += v[i]; }
    float mean = block_sum(s, sh) * (1.0f / D_MODEL);
    float q = 0.f;
    #pragma unroll
    for (int i = 0; i < 4; i++) { float d = v[i] - mean; q += d * d; }
    float var = block_sum(q, sh) * (1.0f / D_MODEL);
    float rstd = rsqrtf(var + 1e-5f);
    __half* y = out + row * D_MODEL;
    #pragma unroll
    for (int i = 0; i < 4; i++) {
        int c = threadIdx.x + i * 256;
        y[c] = __float2half_rn((v[i] - mean) * rstd * gamma[c] + beta[c]);
    }
}

// ---------------- softmax over fp16 rows (in place, vectorized uint4) --------
__global__ __launch_bounds__(256) void softmax_kernel(__half* __restrict__ sc)
{
    __shared__ float sh[32];
    size_t row = blockIdx.x;
    __half* p = sc + row * (size_t)SEQ;
    uint4 u = ((const uint4*)p)[threadIdx.x];
    __half2* hp = (__half2*)&u;
    float v[8], m = -3.4e38f;
    #pragma unroll
    for (int i = 0; i < 4; i++) {
        float2 f = __half22float2(hp[i]);
        v[2 * i] = f.x; v[2 * i + 1] = f.y;
        m = fmaxf(m, fmaxf(f.x, f.y));
    }
    m = block_max(m, sh);
    float s = 0.f;
    #pragma unroll
    for (int i = 0; i < 8; i++) { v[i] = __expf(v[i] - m); s += v[i]; }
    s = block_sum(s, sh);
    float inv = 1.0f / s;
    #pragma unroll
    for (int i = 0; i < 4; i++)
        hp[i] = __floats2half2_rn(v[2 * i] * inv, v[2 * i + 1] * inv);
    ((uint4*)p)[threadIdx.x] = u;
}

// ---------------- mirror upper-triangular 128-blocks to lower ----------------
__global__ __launch_bounds__(256) void mirror_kernel(__half* __restrict__ sc)
{
    if ((blockIdx.y >> 2) <= (blockIdx.x >> 2)) return;   // strict lower 128-blocks only
    __half* p = sc + blockIdx.z * (size_t)SEQ * SEQ;
    __shared__ __half t[32][33];
    int tx = threadIdx.x & 31, ty = threadIdx.x >> 5;
    int R0 = blockIdx.y * 32, C0 = blockIdx.x * 32;
    #pragma unroll
    for (int i = 0; i < 4; i++)
        t[ty + i * 8][tx] = p[(size_t)(C0 + ty + i * 8) * SEQ + R0 + tx];
    __syncthreads();
    #pragma unroll
    for (int i = 0; i < 4; i++)
        p[(size_t)(R0 + ty + i * 8) * SEQ + C0 + tx] = t[tx][ty + i * 8];
}

// ---------------- tiled transpose + convert: out[C][R] = cvt(in[R][C])^T ------
template<typename TIN>
__global__ __launch_bounds__(256) void transpose_cvt(
    const TIN* __restrict__ in, __half* __restrict__ out,
    int R, int C, size_t sI, size_t sO)
{
    in += blockIdx.z * sI; out += blockIdx.z * sO;
    __shared__ float t[32][33];
    int tx = threadIdx.x & 31, ty = threadIdx.x >> 5;
    int c = blockIdx.x * 32 + tx;
    int r0 = blockIdx.y * 32;
    #pragma unroll
    for (int i = 0; i < 4; i++)
        t[ty + i * 8][tx] = (float)in[(size_t)(r0 + ty + i * 8) * C + c];
    __syncthreads();
    int rc = r0 + tx;
    int oc0 = blockIdx.x * 32;
    #pragma unroll
    for (int i = 0; i < 4; i++)
        out[(size_t)(oc0 + ty + i * 8) * R + rc] = __float2half_rn(t[tx][ty + i * 8]);
}

// ======================= FP16 HMMA GEMM (NT, ldmatrix, BK=32) =================
// C[M,N] = A[M,K] @ Bt[N,K]^T, operands fp16, accumulate fp32.
// Block 128x128, 128 threads = 4 warps 2x2, warp tile 64x64,
// mma.sync.m16n8k16, BK=32 double-buffered, smem row stride 20 words (CF).
// SYMM: skip CTAs with bx<by (mirror fills them).
// EPI: 0 scale -> TOUT   1 gelu(+bias) -> half   2 +bias+resid -> float   3 +resid -> float

__device__ __forceinline__ uint32_t smem_u32(const void* p) {
    uint32_t a;
    asm("{ .reg .u64 t; cvta.to.shared.u64 t, %1; cvt.u32.u64 %0, t; }" : "=r"(a) : "l"(p));
    return a;
}

__device__ __forceinline__ void ldsm4(uint32_t& r0, uint32_t& r1, uint32_t& r2, uint32_t& r3,
                                      uint32_t addr) {
    asm volatile("ldmatrix.sync.aligned.m8n8.x4.shared.b16 {%0,%1,%2,%3}, [%4];"
                 : "=r"(r0), "=r"(r1), "=r"(r2), "=r"(r3) : "r"(addr));
}

__device__ __forceinline__ void mma16(float* c, const uint32_t* a, const uint32_t* b) {
    asm volatile(
        "mma.sync.aligned.m16n8k16.row.col.f32.f16.f16.f32 "
        "{%0,%1,%2,%3}, {%4,%5,%6,%7}, {%8,%9}, {%0,%1,%2,%3};"
        : "+f"(c[0]), "+f"(c[1]), "+f"(c[2]), "+f"(c[3])
        : "r"(a[0]), "r"(a[1]), "r"(a[2]), "r"(a[3]), "r"(b[0]), "r"(b[1]));
}

__device__ __forceinline__ float gelu_exact(float v) {
    return v * 0.5f * (1.0f + erff(v * 0.70710678118654752f));
}

__device__ __forceinline__ void store2(__half* p, float a, float b) {
    *(__half2*)p = __floats2half2_rn(a, b);
}
__device__ __forceinline__ void store2(float* p, float a, float b) {
    p[0] = a; p[1] = b;
}

#define RSTR 20                       // smem row stride in 32-bit words
#define TILEW (128 * RSTR)            // words per tile buffer
#define TILEBYTES (TILEW * 4)         // 10240

template<int EPI, int SYMM, typename TOUT>
__global__ __launch_bounds__(128, 2) void gemm_f16(
    const __half* __restrict__ A, const __half* __restrict__ Bt, TOUT* __restrict__ C,
    int K, int N, size_t sA, size_t sB, size_t sC,
    const float* __restrict__ bias, const float* __restrict__ resid, float scale)
{
    if (SYMM && blockIdx.x < blockIdx.y) return;

    A += blockIdx.z * sA; Bt += blockIdx.z * sB; C += blockIdx.z * sC;
    if (EPI >= 2) resid += blockIdx.z * sC;

    __shared__ uint32_t As[2][TILEW];
    __shared__ uint32_t Bs[2][TILEW];

    const int tid  = threadIdx.x;
    const int lane = tid & 31;
    const int warp = tid >> 5;
    const int warpM = warp >> 1;
    const int warpN = warp & 1;
    const int r  = lane >> 2;
    const int cq = lane & 3;

    const int row0 = blockIdx.y * 128;
    const int col0 = blockIdx.x * 128;

    const __half* pa = A + (size_t)(row0 + tid) * K;
    const __half* pb = Bt + (size_t)(col0 + tid) * K;

    const uint32_t asBase = smem_u32(As);
    const uint32_t bsBase = smem_u32(Bs);
    uint32_t aAddr[4], bAddr[4];
    {
        int mrow = (lane & 7) + ((lane >> 3) & 1) * 8;
        int seg  = lane >> 4;
        #pragma unroll
        for (int i = 0; i < 4; i++) {
            int m = warpM * 64 + i * 16 + mrow;
            aAddr[i] = asBase + (uint32_t)(m * RSTR + seg * 4) * 4;
        }
        int nrow = (lane & 7) + ((lane >> 4) & 1) * 8;
        int bseg = (lane >> 3) & 1;
        #pragma unroll
        for (int jp = 0; jp < 4; jp++) {
            int n = warpN * 64 + jp * 16 + nrow;
            bAddr[jp] = bsBase + (uint32_t)(n * RSTR + bseg * 4) * 4;
        }
    }

    float acc[4][8][4] = {};
    uint4 ra[4], rb[4];

    auto ldg_tile = [&](int c) {
        const uint4* qa = (const uint4*)(pa + c * 32);
        const uint4* qb = (const uint4*)(pb + c * 32);
        #pragma unroll
        for (int i = 0; i < 4; i++) { ra[i] = qa[i]; rb[i] = qb[i]; }
    };
    auto sts_tile = [&](int nb) {
        #pragma unroll
        for (int i = 0; i < 4; i++) {
            *(uint4*)&As[nb][tid * RSTR + i * 4] = ra[i];
            *(uint4*)&Bs[nb][tid * RSTR + i * 4] = rb[i];
        }
    };

    ldg_tile(0);
    sts_tile(0);
    __syncthreads();

    const int nch = K / 32;
    int buf = 0;
    for (int c = 0; c < nch; c++) {
        const bool more = (c + 1 < nch);
        if (more) ldg_tile(c + 1);

        const uint32_t bo = (uint32_t)buf * TILEBYTES;
        uint32_t af[2][4][4], bf[2][8][2];
        #pragma unroll
        for (int s = 0; s < 2; s++) {
            const uint32_t so = bo + (uint32_t)s * 32;
            #pragma unroll
            for (int i = 0; i < 4; i++)
                ldsm4(af[s][i][0], af[s][i][1], af[s][i][2], af[s][i][3], aAddr[i] + so);
            #pragma unroll
            for (int jp = 0; jp < 4; jp++)
                ldsm4(bf[s][2 * jp][0], bf[s][2 * jp][1],
                      bf[s][2 * jp + 1][0], bf[s][2 * jp + 1][1], bAddr[jp] + so);
        }
        #pragma unroll
        for (int s = 0; s < 2; s++)
            #pragma unroll
            for (int i = 0; i < 4; i++)
                #pragma unroll
                for (int j = 0; j < 8; j++)
                    mma16(acc[i][j], af[s][i], bf[s][j]);

        if (more) {
            sts_tile(buf ^ 1);
            __syncthreads();
            buf ^= 1;
        }
    }

    // ---- epilogue ----
    #pragma unroll
    for (int i = 0; i < 4; i++) {
        int mrow = row0 + warpM * 64 + i * 16 + r;
        #pragma unroll
        for (int j = 0; j < 8; j++) {
            int ncol = col0 + warpN * 64 + j * 8 + 2 * cq;
            float v0 = acc[i][j][0], v1 = acc[i][j][1];
            float v2 = acc[i][j][2], v3 = acc[i][j][3];
            size_t p0 = (size_t)mrow * N + ncol;
            size_t p1 = (size_t)(mrow + 8) * N + ncol;
            if (EPI == 0) {
                v0 *= scale; v1 *= scale; v2 *= scale; v3 *= scale;
            } else if (EPI == 3) {
                v0 += resid[p0];     v1 += resid[p0 + 1];
                v2 += resid[p1];     v3 += resid[p1 + 1];
            } else {
                float bb0 = bias[ncol], bb1 = bias[ncol + 1];
                if (EPI == 1) {
                    v0 = gelu_exact(v0 + bb0); v1 = gelu_exact(v1 + bb1);
                    v2 = gelu_exact(v2 + bb0); v3 = gelu_exact(v3 + bb1);
                } else {
                    v0 += bb0 + resid[p0];     v1 += bb1 + resid[p0 + 1];
                    v2 += bb0 + resid[p1];     v3 += bb1 + resid[p1 + 1];
                }
            }
            store2(C + p0, v0, v1);
            store2(C + p1, v2, v3);
        }
    }
}

// ---------------- launch ----------------
extern "C" void kernel_launch(void* const* d_in, const int* in_sizes, int n_in,
                              void* d_out, int out_size)
{
    const float* src    = (const float*)d_in[0];
    const float* gamma1 = (const float*)d_in[1];
    const float* beta1  = (const float*)d_in[2];
    const float* gamma2 = (const float*)d_in[3];
    const float* beta2  = (const float*)d_in[4];
    const float* w1     = (const float*)d_in[5];
    const float* b1     = (const float*)d_in[6];
    const float* w2     = (const float*)d_in[7];
    const float* b2     = (const float*)d_in[8];
    float* out = (float*)d_out;

    __half *norm1, *norm1t, *scores, *norm2, *h, *w1t, *w2t;
    float *x;
    cudaGetSymbolAddress((void**)&norm1, g_norm1);
    cudaGetSymbolAddress((void**)&norm1t, g_norm1t);
    cudaGetSymbolAddress((void**)&scores, g_scores);
    cudaGetSymbolAddress((void**)&x, g_x);
    cudaGetSymbolAddress((void**)&norm2, g_norm2);
    cudaGetSymbolAddress((void**)&h, g_h);
    cudaGetSymbolAddress((void**)&w1t, g_w1t);
    cudaGetSymbolAddress((void**)&w2t, g_w2t);

    // side stream + events (host objects, created once; no device memory)
    static cudaStream_t s2 = nullptr;
    static cudaEvent_t e0 = nullptr, eLN = nullptr, e1 = nullptr;
    if (!s2) {
        cudaStreamCreateWithFlags(&s2, cudaStreamNonBlocking);
        cudaEventCreateWithFlags(&e0, cudaEventDisableTiming);
        cudaEventCreateWithFlags(&eLN, cudaEventDisableTiming);
        cudaEventCreateWithFlags(&e1, cudaEventDisableTiming);
    }

    const size_t SD = (size_t)SEQ * D_MODEL;
    const size_t SS = (size_t)SEQ * SEQ;

    // fork side stream at entry
    cudaEventRecord(e0, 0);
    cudaStreamWaitEvent(s2, e0, 0);

    // side stream: weight transposes (needed only at steps 6/7)
    transpose_cvt<float><<<dim3(D_FF / 32, D_MODEL / 32, 1), 256, 0, s2>>>(
        w1, w1t, D_MODEL, D_FF, 0, 0);
    transpose_cvt<float><<<dim3(D_MODEL / 32, D_FF / 32, 1), 256, 0, s2>>>(
        w2, w2t, D_FF, D_MODEL, 0, 0);

    // 1. norm1 = LN(src) -> fp16   (main stream)
    ln_kernel<<<NTOK, 256>>>(src, gamma1, beta1, norm1);
    cudaEventRecord(eLN, 0);

    // side stream: norm1t (needed only at step 4)
    cudaStreamWaitEvent(s2, eLN, 0);
    transpose_cvt<__half><<<dim3(D_MODEL / 32, SEQ / 32, BATCH), 256, 0, s2>>>(
        norm1, norm1t, SEQ, D_MODEL, SD, SD);
    cudaEventRecord(e1, s2);

    // 2. scores upper blocks  (main stream, overlaps side stream)
    gemm_f16<0, 1, __half><<<dim3(SEQ / 128, SEQ / 128, BATCH), 128>>>(
        norm1, norm1, scores, D_MODEL, SEQ, SD, SD, SS, nullptr, nullptr, 0.03125f);

    // 2b. mirror to lower blocks (bitwise exact)
    mirror_kernel<<<dim3(SEQ / 32, SEQ / 32, BATCH), 256>>>(scores);

    // 3. softmax rows
    softmax_kernel<<<BATCH * SEQ, 256>>>(scores);

    // join side stream before attn GEMM
    cudaStreamWaitEvent(0, e1, 0);

    // 4. x[b] = probs[b] @ norm1[b] + src[b]   (EPI 3, fused residual) -> fp32
    gemm_f16<3, 0, float><<<dim3(D_MODEL / 128, SEQ / 128, BATCH), 128>>>(
        scores, norm1t, x, SEQ, D_MODEL, SS, SD, SD, nullptr, src, 1.0f);

    // 5. norm2 = LN(x) -> fp16
    ln_kernel<<<NTOK, 256>>>(x, gamma2, beta2, norm2);

    // 6. h = gelu(norm2 @ w1 + b1)  (B = w1t) -> fp16
    gemm_f16<1, 0, __half><<<dim3(D_FF / 128, NTOK / 128, 1), 128>>>(
        norm2, w1t, h, D_MODEL, D_FF, 0, 0, 0, b1, nullptr, 1.0f);

    // 7. out = h @ w2 + b2 + x  (B = w2t) -> fp32
    gemm_f16<2, 0, float><<<dim3(D_MODEL / 128, NTOK / 128, 1), 128>>>(
        h, w2t, out, D_FF, D_MODEL, 0, 0, 0, b2, x, 1.0f);

    (void)in_sizes; (void)n_in; (void)out_size;
}

// round 16
// speedup vs baseline: 1.1516x; 1.0013x over previous
#include <cuda_runtime.h>
#include <cuda_fp16.h>
#include <math.h>
#include <stdint.h>

#define D_MODEL 1024
#define D_FF    4096
#define BATCH   4
#define SEQ     2048
#define NTOK    (BATCH * SEQ)   // 8192

// ---------------- scratch (allocation-free: __device__ globals) ----------------
__device__ __half g_norm1[(size_t)NTOK * D_MODEL];
__device__ __half g_norm1t[(size_t)NTOK * D_MODEL];      // per-batch [D][S]
__device__ __half g_scores[(size_t)BATCH * SEQ * SEQ];   // scores then probs
__device__ float  g_x[(size_t)NTOK * D_MODEL];
__device__ __half g_norm2[(size_t)NTOK * D_MODEL];
__device__ __half g_h[(size_t)NTOK * D_FF];
__device__ __half g_w1t[(size_t)D_FF * D_MODEL];         // [ff][d]
__device__ __half g_w2t[(size_t)D_MODEL * D_FF];         // [d][ff]

// ---------------- reductions ----------------
__device__ __forceinline__ float block_sum(float v, float* sh) {
    int lane = threadIdx.x & 31, w = threadIdx.x >> 5;
    #pragma unroll
    for (int o = 16; o; o >>= 1) v += __shfl_down_sync(0xffffffffu, v, o);
    if (lane == 0) sh[w] = v;
    __syncthreads();
    if (w == 0) {
        float t = (lane < 8) ? sh[lane] : 0.f;
        #pragma unroll
        for (int o = 4; o; o >>= 1) t += __shfl_down_sync(0xffffffffu, t, o);
        if (lane == 0) sh[0] = t;
    }
    __syncthreads();
    float r = sh[0];
    __syncthreads();
    return r;
}

__device__ __forceinline__ float block_max(float v, float* sh) {
    int lane = threadIdx.x & 31, w = threadIdx.x >> 5;
    #pragma unroll
    for (int o = 16; o; o >>= 1) v = fmaxf(v, __shfl_down_sync(0xffffffffu, v, o));
    if (lane == 0) sh[w] = v;
    __syncthreads();
    if (w == 0) {
        float t = (lane < 8) ? sh[lane] : -3.4e38f;
        #pragma unroll
        for (int o = 4; o; o >>= 1) t = fmaxf(t, __shfl_down_sync(0xffffffffu, t, o));
        if (lane == 0) sh[0] = t;
    }
    __syncthreads();
    float r = sh[0];
    __syncthreads();
    return r;
}

// ---------------- LayerNorm (fp32 in, fp16 out, vectorized) ----------------
// thread t handles cols 4t..4t+3 (float4 load, 8B fp16 store)
__global__ __launch_bounds__(256) void ln_kernel(
    const float* __restrict__ in, const float* __restrict__ gamma,
    const float* __restrict__ beta, __half* __restrict__ out)
{
    __shared__ float sh[32];
    size_t row = blockIdx.x;
    const int c0 = threadIdx.x * 4;
    float4 v = *(const float4*)(in + row * D_MODEL + c0);
    float s = v.x + v.y + v.z + v.w;
    float mean = block_sum(s, sh) * (1.0f / D_MODEL);
    float dx = v.x - mean, dy = v.y - mean, dz = v.z - mean, dw = v.w - mean;
    float q = dx * dx + dy * dy + dz * dz + dw * dw;
    float var = block_sum(q, sh) * (1.0f / D_MODEL);
    float rstd = rsqrtf(var + 1e-5f);
    float4 g = *(const float4*)(gamma + c0);
    float4 b = *(const float4*)(beta + c0);
    __half2 h0 = __floats2half2_rn(dx * rstd * g.x + b.x, dy * rstd * g.y + b.y);
    __half2 h1 = __floats2half2_rn(dz * rstd * g.z + b.z, dw * rstd * g.w + b.w);
    uint2 u; u.x = *(uint32_t*)&h0; u.y = *(uint32_t*)&h1;
    *(uint2*)(out + row * D_MODEL + c0) = u;
}

// ---------------- softmax over fp16 rows (in place, vectorized uint4) --------
__global__ __launch_bounds__(256) void softmax_kernel(__half* __restrict__ sc)
{
    __shared__ float sh[32];
    size_t row = blockIdx.x;
    __half* p = sc + row * (size_t)SEQ;
    uint4 u = ((const uint4*)p)[threadIdx.x];
    __half2* hp = (__half2*)&u;
    float v[8], m = -3.4e38f;
    #pragma unroll
    for (int i = 0; i < 4; i++) {
        float2 f = __half22float2(hp[i]);
        v[2 * i] = f.x; v[2 * i + 1] = f.y;
        m = fmaxf(m, fmaxf(f.x, f.y));
    }
    m = block_max(m, sh);
    float s = 0.f;
    #pragma unroll
    for (int i = 0; i < 8; i++) { v[i] = __expf(v[i] - m); s += v[i]; }
    s = block_sum(s, sh);
    float inv = 1.0f / s;
    #pragma unroll
    for (int i = 0; i < 4; i++)
        hp[i] = __floats2half2_rn(v[2 * i] * inv, v[2 * i + 1] * inv);
    ((uint4*)p)[threadIdx.x] = u;
}

// ---------------- mirror: compacted to strict-lower 128-block pairs ----------
// blockIdx.x = pair id (0..119) -> (rB,cB) strict lower; blockIdx.y = 4x4 sub.
__global__ __launch_bounds__(256) void mirror_kernel(__half* __restrict__ sc)
{
    int b = blockIdx.x, cB = 0;
    while (b >= 15 - cB) { b -= 15 - cB; cB++; }   // strict lower: rB in (cB,16)
    int rB = cB + 1 + b;
    int R0 = rB * 128 + (blockIdx.y >> 2) * 32;
    int C0 = cB * 128 + (blockIdx.y & 3) * 32;
    __half* p = sc + blockIdx.z * (size_t)SEQ * SEQ;
    __shared__ __half t[32][33];
    int tx = threadIdx.x & 31, ty = threadIdx.x >> 5;
    #pragma unroll
    for (int i = 0; i < 4; i++)
        t[ty + i * 8][tx] = p[(size_t)(C0 + ty + i * 8) * SEQ + R0 + tx];
    __syncthreads();
    #pragma unroll
    for (int i = 0; i < 4; i++)
        p[(size_t)(R0 + ty + i * 8) * SEQ + C0 + tx] = t[tx][ty + i * 8];
}

// ---------------- tiled transpose + convert: out[C][R] = cvt(in[R][C])^T ------
template<typename TIN>
__global__ __launch_bounds__(256) void transpose_cvt(
    const TIN* __restrict__ in, __half* __restrict__ out,
    int R, int C, size_t sI, size_t sO)
{
    in += blockIdx.z * sI; out += blockIdx.z * sO;
    __shared__ float t[32][33];
    int tx = threadIdx.x & 31, ty = threadIdx.x >> 5;
    int c = blockIdx.x * 32 + tx;
    int r0 = blockIdx.y * 32;
    #pragma unroll
    for (int i = 0; i < 4; i++)
        t[ty + i * 8][tx] = (float)in[(size_t)(r0 + ty + i * 8) * C + c];
    __syncthreads();
    int rc = r0 + tx;
    int oc0 = blockIdx.x * 32;
    #pragma unroll
    for (int i = 0; i < 4; i++)
        out[(size_t)(oc0 + ty + i * 8) * R + rc] = __float2half_rn(t[tx][ty + i * 8]);
}

// ======================= FP16 HMMA GEMM (NT, ldmatrix, BK=32) =================
// C[M,N] = A[M,K] @ Bt[N,K]^T, operands fp16, accumulate fp32.
// Block 128x128, 128 threads = 4 warps 2x2, warp tile 64x64,
// mma.sync.m16n8k16, BK=32 double-buffered, smem row stride 20 words (CF).
// SYMM: triangular-compacted grid (blockIdx.x = upper-pair id incl. diagonal).
// EPI: 0 scale -> TOUT   1 gelu(+bias) -> half   2 +bias+resid -> float   3 +resid -> float

__device__ __forceinline__ uint32_t smem_u32(const void* p) {
    uint32_t a;
    asm("{ .reg .u64 t; cvta.to.shared.u64 t, %1; cvt.u32.u64 %0, t; }" : "=r"(a) : "l"(p));
    return a;
}

__device__ __forceinline__ void ldsm4(uint32_t& r0, uint32_t& r1, uint32_t& r2, uint32_t& r3,
                                      uint32_t addr) {
    asm volatile("ldmatrix.sync.aligned.m8n8.x4.shared.b16 {%0,%1,%2,%3}, [%4];"
                 : "=r"(r0), "=r"(r1), "=r"(r2), "=r"(r3) : "r"(addr));
}

__device__ __forceinline__ void mma16(float* c, const uint32_t* a, const uint32_t* b) {
    asm volatile(
        "mma.sync.aligned.m16n8k16.row.col.f32.f16.f16.f32 "
        "{%0,%1,%2,%3}, {%4,%5,%6,%7}, {%8,%9}, {%0,%1,%2,%3};"
        : "+f"(c[0]), "+f"(c[1]), "+f"(c[2]), "+f"(c[3])
        : "r"(a[0]), "r"(a[1]), "r"(a[2]), "r"(a[3]), "r"(b[0]), "r"(b[1]));
}

__device__ __forceinline__ float gelu_exact(float v) {
    return v * 0.5f * (1.0f + erff(v * 0.70710678118654752f));
}

__device__ __forceinline__ void store2(__half* p, float a, float b) {
    *(__half2*)p = __floats2half2_rn(a, b);
}
__device__ __forceinline__ void store2(float* p, float a, float b) {
    p[0] = a; p[1] = b;
}

#define RSTR 20                       // smem row stride in 32-bit words
#define TILEW (128 * RSTR)            // words per tile buffer
#define TILEBYTES (TILEW * 4)         // 10240

template<int EPI, int SYMM, typename TOUT>
__global__ __launch_bounds__(128, 2) void gemm_f16(
    const __half* __restrict__ A, const __half* __restrict__ Bt, TOUT* __restrict__ C,
    int K, int N, size_t sA, size_t sB, size_t sC,
    const float* __restrict__ bias, const float* __restrict__ resid, float scale)
{
    int bx, by;
    if (SYMM) {
        // triangular decode: blockIdx.x -> (by, bx) with bx >= by over 16x16 blocks
        int b = blockIdx.x;
        by = 0;
        while (b >= 16 - by) { b -= 16 - by; by++; }
        bx = by + b;
    } else {
        bx = blockIdx.x; by = blockIdx.y;
    }

    A += blockIdx.z * sA; Bt += blockIdx.z * sB; C += blockIdx.z * sC;
    if (EPI >= 2) resid += blockIdx.z * sC;

    __shared__ uint32_t As[2][TILEW];
    __shared__ uint32_t Bs[2][TILEW];

    const int tid  = threadIdx.x;
    const int lane = tid & 31;
    const int warp = tid >> 5;
    const int warpM = warp >> 1;
    const int warpN = warp & 1;
    const int r  = lane >> 2;
    const int cq = lane & 3;

    const int row0 = by * 128;
    const int col0 = bx * 128;

    const __half* pa = A + (size_t)(row0 + tid) * K;
    const __half* pb = Bt + (size_t)(col0 + tid) * K;

    const uint32_t asBase = smem_u32(As);
    const uint32_t bsBase = smem_u32(Bs);
    uint32_t aAddr[4], bAddr[4];
    {
        int mrow = (lane & 7) + ((lane >> 3) & 1) * 8;
        int seg  = lane >> 4;
        #pragma unroll
        for (int i = 0; i < 4; i++) {
            int m = warpM * 64 + i * 16 + mrow;
            aAddr[i] = asBase + (uint32_t)(m * RSTR + seg * 4) * 4;
        }
        int nrow = (lane & 7) + ((lane >> 4) & 1) * 8;
        int bseg = (lane >> 3) & 1;
        #pragma unroll
        for (int jp = 0; jp < 4; jp++) {
            int n = warpN * 64 + jp * 16 + nrow;
            bAddr[jp] = bsBase + (uint32_t)(n * RSTR + bseg * 4) * 4;
        }
    }

    float acc[4][8][4] = {};
    uint4 ra[4], rb[4];

    auto ldg_tile = [&](int c) {
        const uint4* qa = (const uint4*)(pa + c * 32);
        const uint4* qb = (const uint4*)(pb + c * 32);
        #pragma unroll
        for (int i = 0; i < 4; i++) { ra[i] = qa[i]; rb[i] = qb[i]; }
    };
    auto sts_tile = [&](int nb) {
        #pragma unroll
        for (int i = 0; i < 4; i++) {
            *(uint4*)&As[nb][tid * RSTR + i * 4] = ra[i];
            *(uint4*)&Bs[nb][tid * RSTR + i * 4] = rb[i];
        }
    };

    ldg_tile(0);
    sts_tile(0);
    __syncthreads();

    const int nch = K / 32;
    int buf = 0;
    for (int c = 0; c < nch; c++) {
        const bool more = (c + 1 < nch);
        if (more) ldg_tile(c + 1);

        const uint32_t bo = (uint32_t)buf * TILEBYTES;
        uint32_t af[2][4][4], bf[2][8][2];
        #pragma unroll
        for (int s = 0; s < 2; s++) {
            const uint32_t so = bo + (uint32_t)s * 32;
            #pragma unroll
            for (int i = 0; i < 4; i++)
                ldsm4(af[s][i][0], af[s][i][1], af[s][i][2], af[s][i][3], aAddr[i] + so);
            #pragma unroll
            for (int jp = 0; jp < 4; jp++)
                ldsm4(bf[s][2 * jp][0], bf[s][2 * jp][1],
                      bf[s][2 * jp + 1][0], bf[s][2 * jp + 1][1], bAddr[jp] + so);
        }
        #pragma unroll
        for (int s = 0; s < 2; s++)
            #pragma unroll
            for (int i = 0; i < 4; i++)
                #pragma unroll
                for (int j = 0; j < 8; j++)
                    mma16(acc[i][j], af[s][i], bf[s][j]);

        if (more) {
            sts_tile(buf ^ 1);
            __syncthreads();
            buf ^= 1;
        }
    }

    // ---- epilogue ----
    #pragma unroll
    for (int i = 0; i < 4; i++) {
        int mrow = row0 + warpM * 64 + i * 16 + r;
        #pragma unroll
        for (int j = 0; j < 8; j++) {
            int ncol = col0 + warpN * 64 + j * 8 + 2 * cq;
            float v0 = acc[i][j][0], v1 = acc[i][j][1];
            float v2 = acc[i][j][2], v3 = acc[i][j][3];
            size_t p0 = (size_t)mrow * N + ncol;
            size_t p1 = (size_t)(mrow + 8) * N + ncol;
            if (EPI == 0) {
                v0 *= scale; v1 *= scale; v2 *= scale; v3 *= scale;
            } else if (EPI == 3) {
                v0 += resid[p0];     v1 += resid[p0 + 1];
                v2 += resid[p1];     v3 += resid[p1 + 1];
            } else {
                float bb0 = bias[ncol], bb1 = bias[ncol + 1];
                if (EPI == 1) {
                    v0 = gelu_exact(v0 + bb0); v1 = gelu_exact(v1 + bb1);
                    v2 = gelu_exact(v2 + bb0); v3 = gelu_exact(v3 + bb1);
                } else {
                    v0 += bb0 + resid[p0];     v1 += bb1 + resid[p0 + 1];
                    v2 += bb0 + resid[p1];     v3 += bb1 + resid[p1 + 1];
                }
            }
            store2(C + p0, v0, v1);
            store2(C + p1, v2, v3);
        }
    }
}

// ---------------- launch ----------------
extern "C" void kernel_launch(void* const* d_in, const int* in_sizes, int n_in,
                              void* d_out, int out_size)
{
    const float* src    = (const float*)d_in[0];
    const float* gamma1 = (const float*)d_in[1];
    const float* beta1  = (const float*)d_in[2];
    const float* gamma2 = (const float*)d_in[3];
    const float* beta2  = (const float*)d_in[4];
    const float* w1     = (const float*)d_in[5];
    const float* b1     = (const float*)d_in[6];
    const float* w2     = (const float*)d_in[7];
    const float* b2     = (const float*)d_in[8];
    float* out = (float*)d_out;

    __half *norm1, *norm1t, *scores, *norm2, *h, *w1t, *w2t;
    float *x;
    cudaGetSymbolAddress((void**)&norm1, g_norm1);
    cudaGetSymbolAddress((void**)&norm1t, g_norm1t);
    cudaGetSymbolAddress((void**)&scores, g_scores);
    cudaGetSymbolAddress((void**)&x, g_x);
    cudaGetSymbolAddress((void**)&norm2, g_norm2);
    cudaGetSymbolAddress((void**)&h, g_h);
    cudaGetSymbolAddress((void**)&w1t, g_w1t);
    cudaGetSymbolAddress((void**)&w2t, g_w2t);

    // side stream + events (host objects, created once; no device memory)
    static cudaStream_t s2 = nullptr;
    static cudaEvent_t e0 = nullptr, eLN = nullptr, e1 = nullptr;
    if (!s2) {
        cudaStreamCreateWithFlags(&s2, cudaStreamNonBlocking);
        cudaEventCreateWithFlags(&e0, cudaEventDisableTiming);
        cudaEventCreateWithFlags(&eLN, cudaEventDisableTiming);
        cudaEventCreateWithFlags(&e1, cudaEventDisableTiming);
    }

    const size_t SD = (size_t)SEQ * D_MODEL;
    const size_t SS = (size_t)SEQ * SEQ;

    // fork side stream at entry
    cudaEventRecord(e0, 0);
    cudaStreamWaitEvent(s2, e0, 0);

    // side stream: weight transposes (needed only at steps 6/7)
    transpose_cvt<float><<<dim3(D_FF / 32, D_MODEL / 32, 1), 256, 0, s2>>>(
        w1, w1t, D_MODEL, D_FF, 0, 0);
    transpose_cvt<float><<<dim3(D_MODEL / 32, D_FF / 32, 1), 256, 0, s2>>>(
        w2, w2t, D_FF, D_MODEL, 0, 0);

    // 1. norm1 = LN(src) -> fp16   (main stream)
    ln_kernel<<<NTOK, 256>>>(src, gamma1, beta1, norm1);
    cudaEventRecord(eLN, 0);

    // side stream: norm1t (needed only at step 4)
    cudaStreamWaitEvent(s2, eLN, 0);
    transpose_cvt<__half><<<dim3(D_MODEL / 32, SEQ / 32, BATCH), 256, 0, s2>>>(
        norm1, norm1t, SEQ, D_MODEL, SD, SD);
    cudaEventRecord(e1, s2);

    // 2. scores upper blocks (triangular-compacted grid: 136 pairs per batch)
    gemm_f16<0, 1, __half><<<dim3(136, 1, BATCH), 128>>>(
        norm1, norm1, scores, D_MODEL, SEQ, SD, SD, SS, nullptr, nullptr, 0.03125f);

    // 2b. mirror to lower blocks (bitwise exact; compacted: 120 pairs x 16 subtiles)
    mirror_kernel<<<dim3(120, 16, BATCH), 256>>>(scores);

    // 3. softmax rows
    softmax_kernel<<<BATCH * SEQ, 256>>>(scores);

    // join side stream before attn GEMM
    cudaStreamWaitEvent(0, e1, 0);

    // 4. x[b] = probs[b] @ norm1[b] + src[b]   (EPI 3, fused residual) -> fp32
    gemm_f16<3, 0, float><<<dim3(D_MODEL / 128, SEQ / 128, BATCH), 128>>>(
        scores, norm1t, x, SEQ, D_MODEL, SS, SD, SD, nullptr, src, 1.0f);

    // 5. norm2 = LN(x) -> fp16
    ln_kernel<<<NTOK, 256>>>(x, gamma2, beta2, norm2);

    // 6. h = gelu(norm2 @ w1 + b1)  (B = w1t) -> fp16
    gemm_f16<1, 0, __half><<<dim3(D_FF / 128, NTOK / 128, 1), 128>>>(
        norm2, w1t, h, D_MODEL, D_FF, 0, 0, 0, b1, nullptr, 1.0f);

    // 7. out = h @ w2 + b2 + x  (B = w2t) -> fp32
    gemm_f16<2, 0, float><<<dim3(D_MODEL / 128, NTOK / 128, 1), 128>>>(
        h, w2t, out, D_FF, D_MODEL, 0, 0, 0, b2, x, 1.0f);

    (void)in_sizes; (void)n_in; (void)out_size;
}

// round 17
// speedup vs baseline: 1.1562x; 1.0039x over previous
#include <cuda_runtime.h>
#include <cuda_fp16.h>
#include <math.h>
#include <stdint.h>

#define D_MODEL 1024
#define D_FF    4096
#define BATCH   4
#define SEQ     2048
#define NTOK    (BATCH * SEQ)   // 8192

// ---------------- scratch (allocation-free: __device__ globals) ----------------
__device__ __half g_norm1[(size_t)NTOK * D_MODEL];
__device__ __half g_norm1t[(size_t)NTOK * D_MODEL];      // per-batch [D][S]
__device__ __half g_scores[(size_t)BATCH * SEQ * SEQ];   // scores then probs
__device__ float  g_x[(size_t)NTOK * D_MODEL];
__device__ __half g_norm2[(size_t)NTOK * D_MODEL];
__device__ __half g_h[(size_t)NTOK * D_FF];
__device__ __half g_w1t[(size_t)D_FF * D_MODEL];         // [ff][d]
__device__ __half g_w2t[(size_t)D_MODEL * D_FF];         // [d][ff]

// ---------------- reductions ----------------
__device__ __forceinline__ float block_sum(float v, float* sh) {
    int lane = threadIdx.x & 31, w = threadIdx.x >> 5;
    #pragma unroll
    for (int o = 16; o; o >>= 1) v += __shfl_down_sync(0xffffffffu, v, o);
    if (lane == 0) sh[w] = v;
    __syncthreads();
    if (w == 0) {
        float t = (lane < 8) ? sh[lane] : 0.f;
        #pragma unroll
        for (int o = 4; o; o >>= 1) t += __shfl_down_sync(0xffffffffu, t, o);
        if (lane == 0) sh[0] = t;
    }
    __syncthreads();
    float r = sh[0];
    __syncthreads();
    return r;
}

__device__ __forceinline__ float block_max(float v, float* sh) {
    int lane = threadIdx.x & 31, w = threadIdx.x >> 5;
    #pragma unroll
    for (int o = 16; o; o >>= 1) v = fmaxf(v, __shfl_down_sync(0xffffffffu, v, o));
    if (lane == 0) sh[w] = v;
    __syncthreads();
    if (w == 0) {
        float t = (lane < 8) ? sh[lane] : -3.4e38f;
        #pragma unroll
        for (int o = 4; o; o >>= 1) t = fmaxf(t, __shfl_down_sync(0xffffffffu, t, o));
        if (lane == 0) sh[0] = t;
    }
    __syncthreads();
    float r = sh[0];
    __syncthreads();
    return r;
}

// ---------------- LayerNorm (fp32 in, fp16 out, vectorized) ----------------
__global__ __launch_bounds__(256) void ln_kernel(
    const float* __restrict__ in, const float* __restrict__ gamma,
    const float* __restrict__ beta, __half* __restrict__ out)
{
    __shared__ float sh[32];
    size_t row = blockIdx.x;
    const int c0 = threadIdx.x * 4;
    float4 v = *(const float4*)(in + row * D_MODEL + c0);
    float s = v.x + v.y + v.z + v.w;
    float mean = block_sum(s, sh) * (1.0f / D_MODEL);
    float dx = v.x - mean, dy = v.y - mean, dz = v.z - mean, dw = v.w - mean;
    float q = dx * dx + dy * dy + dz * dz + dw * dw;
    float var = block_sum(q, sh) * (1.0f / D_MODEL);
    float rstd = rsqrtf(var + 1e-5f);
    float4 g = *(const float4*)(gamma + c0);
    float4 b = *(const float4*)(beta + c0);
    __half2 h0 = __floats2half2_rn(dx * rstd * g.x + b.x, dy * rstd * g.y + b.y);
    __half2 h1 = __floats2half2_rn(dz * rstd * g.z + b.z, dw * rstd * g.w + b.w);
    uint2 u; u.x = *(uint32_t*)&h0; u.y = *(uint32_t*)&h1;
    *(uint2*)(out + row * D_MODEL + c0) = u;
}

// ---------------- softmax over fp16 rows (in place, vectorized uint4) --------
__global__ __launch_bounds__(256) void softmax_kernel(__half* __restrict__ sc)
{
    __shared__ float sh[32];
    size_t row = blockIdx.x;
    __half* p = sc + row * (size_t)SEQ;
    uint4 u = ((const uint4*)p)[threadIdx.x];
    __half2* hp = (__half2*)&u;
    float v[8], m = -3.4e38f;
    #pragma unroll
    for (int i = 0; i < 4; i++) {
        float2 f = __half22float2(hp[i]);
        v[2 * i] = f.x; v[2 * i + 1] = f.y;
        m = fmaxf(m, fmaxf(f.x, f.y));
    }
    m = block_max(m, sh);
    float s = 0.f;
    #pragma unroll
    for (int i = 0; i < 8; i++) { v[i] = __expf(v[i] - m); s += v[i]; }
    s = block_sum(s, sh);
    float inv = 1.0f / s;
    #pragma unroll
    for (int i = 0; i < 4; i++)
        hp[i] = __floats2half2_rn(v[2 * i] * inv, v[2 * i + 1] * inv);
    ((uint4*)p)[threadIdx.x] = u;
}

// ---------------- tiled transpose + convert: out[C][R] = cvt(in[R][C])^T ------
template<typename TIN>
__global__ __launch_bounds__(256) void transpose_cvt(
    const TIN* __restrict__ in, __half* __restrict__ out,
    int R, int C, size_t sI, size_t sO)
{
    in += blockIdx.z * sI; out += blockIdx.z * sO;
    __shared__ float t[32][33];
    int tx = threadIdx.x & 31, ty = threadIdx.x >> 5;
    int c = blockIdx.x * 32 + tx;
    int r0 = blockIdx.y * 32;
    #pragma unroll
    for (int i = 0; i < 4; i++)
        t[ty + i * 8][tx] = (float)in[(size_t)(r0 + ty + i * 8) * C + c];
    __syncthreads();
    int rc = r0 + tx;
    int oc0 = blockIdx.x * 32;
    #pragma unroll
    for (int i = 0; i < 4; i++)
        out[(size_t)(oc0 + ty + i * 8) * R + rc] = __float2half_rn(t[tx][ty + i * 8]);
}

// ======================= FP16 HMMA GEMM (NT, ldmatrix, BK=32) =================
// C[M,N] = A[M,K] @ Bt[N,K]^T, operands fp16, accumulate fp32.
// Block 128x128, 128 threads = 4 warps 2x2, warp tile 64x64,
// mma.sync.m16n8k16, BK=32 double-buffered, smem row stride 20 words (CF).
// SYMM: triangular-compacted grid; off-diagonal CTAs also write the mirrored
//       (transposed) lower tile via smem staging -- no separate mirror kernel.
// EPI: 0 scale -> TOUT   1 gelu(+bias) -> half   2 +bias+resid -> float   3 +resid -> float

__device__ __forceinline__ uint32_t smem_u32(const void* p) {
    uint32_t a;
    asm("{ .reg .u64 t; cvta.to.shared.u64 t, %1; cvt.u32.u64 %0, t; }" : "=r"(a) : "l"(p));
    return a;
}

__device__ __forceinline__ void ldsm4(uint32_t& r0, uint32_t& r1, uint32_t& r2, uint32_t& r3,
                                      uint32_t addr) {
    asm volatile("ldmatrix.sync.aligned.m8n8.x4.shared.b16 {%0,%1,%2,%3}, [%4];"
                 : "=r"(r0), "=r"(r1), "=r"(r2), "=r"(r3) : "r"(addr));
}

__device__ __forceinline__ void mma16(float* c, const uint32_t* a, const uint32_t* b) {
    asm volatile(
        "mma.sync.aligned.m16n8k16.row.col.f32.f16.f16.f32 "
        "{%0,%1,%2,%3}, {%4,%5,%6,%7}, {%8,%9}, {%0,%1,%2,%3};"
        : "+f"(c[0]), "+f"(c[1]), "+f"(c[2]), "+f"(c[3])
        : "r"(a[0]), "r"(a[1]), "r"(a[2]), "r"(a[3]), "r"(b[0]), "r"(b[1]));
}

__device__ __forceinline__ float gelu_exact(float v) {
    return v * 0.5f * (1.0f + erff(v * 0.70710678118654752f));
}

__device__ __forceinline__ void store2(__half* p, float a, float b) {
    *(__half2*)p = __floats2half2_rn(a, b);
}
__device__ __forceinline__ void store2(float* p, float a, float b) {
    p[0] = a; p[1] = b;
}

#define RSTR 20                       // smem row stride in 32-bit words
#define TILEW (128 * RSTR)            // words per tile buffer
#define TILEBYTES (TILEW * 4)         // 10240
#define MSTR 136                      // mirror staging row stride (halves)

template<int EPI, int SYMM, typename TOUT>
__global__ __launch_bounds__(128, 2) void gemm_f16(
    const __half* __restrict__ A, const __half* __restrict__ Bt, TOUT* __restrict__ C,
    int K, int N, size_t sA, size_t sB, size_t sC,
    const float* __restrict__ bias, const float* __restrict__ resid, float scale)
{
    int bx, by;
    if (SYMM) {
        int b = blockIdx.x;
        by = 0;
        while (b >= 16 - by) { b -= 16 - by; by++; }
        bx = by + b;
    } else {
        bx = blockIdx.x; by = blockIdx.y;
    }

    A += blockIdx.z * sA; Bt += blockIdx.z * sB; C += blockIdx.z * sC;
    if (EPI >= 2) resid += blockIdx.z * sC;

    // unified smem: tile buffers during mainloop, mirror staging in epilogue
    __shared__ uint32_t sm4[4 * TILEW];   // 40960 B >= 128*MSTR*2 = 34816 B

    const int tid  = threadIdx.x;
    const int lane = tid & 31;
    const int warp = tid >> 5;
    const int warpM = warp >> 1;
    const int warpN = warp & 1;
    const int r  = lane >> 2;
    const int cq = lane & 3;

    const int row0 = by * 128;
    const int col0 = bx * 128;

    const __half* pa = A + (size_t)(row0 + tid) * K;
    const __half* pb = Bt + (size_t)(col0 + tid) * K;

    const uint32_t asBase = smem_u32(sm4);                     // As buffers
    const uint32_t bsBase = asBase + 2 * TILEBYTES;            // Bs buffers
    uint32_t aAddr[4], bAddr[4];
    {
        int mrow = (lane & 7) + ((lane >> 3) & 1) * 8;
        int seg  = lane >> 4;
        #pragma unroll
        for (int i = 0; i < 4; i++) {
            int m = warpM * 64 + i * 16 + mrow;
            aAddr[i] = asBase + (uint32_t)(m * RSTR + seg * 4) * 4;
        }
        int nrow = (lane & 7) + ((lane >> 4) & 1) * 8;
        int bseg = (lane >> 3) & 1;
        #pragma unroll
        for (int jp = 0; jp < 4; jp++) {
            int n = warpN * 64 + jp * 16 + nrow;
            bAddr[jp] = bsBase + (uint32_t)(n * RSTR + bseg * 4) * 4;
        }
    }

    float acc[4][8][4] = {};
    uint4 ra[4], rb[4];

    auto ldg_tile = [&](int c) {
        const uint4* qa = (const uint4*)(pa + c * 32);
        const uint4* qb = (const uint4*)(pb + c * 32);
        #pragma unroll
        for (int i = 0; i < 4; i++) { ra[i] = qa[i]; rb[i] = qb[i]; }
    };
    auto sts_tile = [&](int nb) {
        uint32_t* Asb = sm4 + nb * TILEW;
        uint32_t* Bsb = sm4 + 2 * TILEW + nb * TILEW;
        #pragma unroll
        for (int i = 0; i < 4; i++) {
            *(uint4*)&Asb[tid * RSTR + i * 4] = ra[i];
            *(uint4*)&Bsb[tid * RSTR + i * 4] = rb[i];
        }
    };

    ldg_tile(0);
    sts_tile(0);
    __syncthreads();

    const int nch = K / 32;
    int buf = 0;
    for (int c = 0; c < nch; c++) {
        const bool more = (c + 1 < nch);
        if (more) ldg_tile(c + 1);

        const uint32_t bo = (uint32_t)buf * TILEBYTES;
        uint32_t af[2][4][4], bf[2][8][2];
        #pragma unroll
        for (int s = 0; s < 2; s++) {
            const uint32_t so = bo + (uint32_t)s * 32;
            #pragma unroll
            for (int i = 0; i < 4; i++)
                ldsm4(af[s][i][0], af[s][i][1], af[s][i][2], af[s][i][3], aAddr[i] + so);
            #pragma unroll
            for (int jp = 0; jp < 4; jp++)
                ldsm4(bf[s][2 * jp][0], bf[s][2 * jp][1],
                      bf[s][2 * jp + 1][0], bf[s][2 * jp + 1][1], bAddr[jp] + so);
        }
        #pragma unroll
        for (int s = 0; s < 2; s++)
            #pragma unroll
            for (int i = 0; i < 4; i++)
                #pragma unroll
                for (int j = 0; j < 8; j++)
                    mma16(acc[i][j], af[s][i], bf[s][j]);

        if (more) {
            sts_tile(buf ^ 1);
            __syncthreads();
            buf ^= 1;
        }
    }

    const bool mirror = SYMM && (bx != by);
    __half* msm = (__half*)sm4;
    if (mirror) __syncthreads();   // tile buffers done; safe to reuse as staging

    // ---- epilogue ----
    #pragma unroll
    for (int i = 0; i < 4; i++) {
        int ml = warpM * 64 + i * 16 + r;        // local m
        int mrow = row0 + ml;
        #pragma unroll
        for (int j = 0; j < 8; j++) {
            int nl = warpN * 64 + j * 8 + 2 * cq;   // local n
            int ncol = col0 + nl;
            float v0 = acc[i][j][0], v1 = acc[i][j][1];
            float v2 = acc[i][j][2], v3 = acc[i][j][3];
            size_t p0 = (size_t)mrow * N + ncol;
            size_t p1 = (size_t)(mrow + 8) * N + ncol;
            if (EPI == 0) {
                v0 *= scale; v1 *= scale; v2 *= scale; v3 *= scale;
            } else if (EPI == 3) {
                v0 += resid[p0];     v1 += resid[p0 + 1];
                v2 += resid[p1];     v3 += resid[p1 + 1];
            } else {
                float bb0 = bias[ncol], bb1 = bias[ncol + 1];
                if (EPI == 1) {
                    v0 = gelu_exact(v0 + bb0); v1 = gelu_exact(v1 + bb1);
                    v2 = gelu_exact(v2 + bb0); v3 = gelu_exact(v3 + bb1);
                } else {
                    v0 += bb0 + resid[p0];     v1 += bb1 + resid[p0 + 1];
                    v2 += bb0 + resid[p1];     v3 += bb1 + resid[p1 + 1];
                }
            }
            store2(C + p0, v0, v1);
            store2(C + p1, v2, v3);
            if (mirror) {
                // staging layout: transposed [n][m], stride MSTR halves
                msm[nl * MSTR + ml]           = __float2half_rn(v0);
                msm[(nl + 1) * MSTR + ml]     = __float2half_rn(v1);
                msm[nl * MSTR + ml + 8]       = __float2half_rn(v2);
                msm[(nl + 1) * MSTR + ml + 8] = __float2half_rn(v3);
            }
        }
    }

    if (mirror) {
        __syncthreads();
        // write transposed tile at (rows col0.., cols row0..), coalesced
        __half* Cm = (__half*)C;
        __half* srow = msm + tid * MSTR;
        __half* drow = Cm + (size_t)(col0 + tid) * N + row0;
        #pragma unroll
        for (int mc = 0; mc < 8; mc++)
            *(uint4*)(drow + mc * 8) = *(uint4*)(srow + mc * 8);
    }
}

// ---------------- launch ----------------
extern "C" void kernel_launch(void* const* d_in, const int* in_sizes, int n_in,
                              void* d_out, int out_size)
{
    const float* src    = (const float*)d_in[0];
    const float* gamma1 = (const float*)d_in[1];
    const float* beta1  = (const float*)d_in[2];
    const float* gamma2 = (const float*)d_in[3];
    const float* beta2  = (const float*)d_in[4];
    const float* w1     = (const float*)d_in[5];
    const float* b1     = (const float*)d_in[6];
    const float* w2     = (const float*)d_in[7];
    const float* b2     = (const float*)d_in[8];
    float* out = (float*)d_out;

    __half *norm1, *norm1t, *scores, *norm2, *h, *w1t, *w2t;
    float *x;
    cudaGetSymbolAddress((void**)&norm1, g_norm1);
    cudaGetSymbolAddress((void**)&norm1t, g_norm1t);
    cudaGetSymbolAddress((void**)&scores, g_scores);
    cudaGetSymbolAddress((void**)&x, g_x);
    cudaGetSymbolAddress((void**)&norm2, g_norm2);
    cudaGetSymbolAddress((void**)&h, g_h);
    cudaGetSymbolAddress((void**)&w1t, g_w1t);
    cudaGetSymbolAddress((void**)&w2t, g_w2t);

    // side stream + events (host objects, created once; no device memory)
    static cudaStream_t s2 = nullptr;
    static cudaEvent_t e0 = nullptr, eLN = nullptr, e1 = nullptr;
    if (!s2) {
        cudaStreamCreateWithFlags(&s2, cudaStreamNonBlocking);
        cudaEventCreateWithFlags(&e0, cudaEventDisableTiming);
        cudaEventCreateWithFlags(&eLN, cudaEventDisableTiming);
        cudaEventCreateWithFlags(&e1, cudaEventDisableTiming);
    }

    const size_t SD = (size_t)SEQ * D_MODEL;
    const size_t SS = (size_t)SEQ * SEQ;

    // fork side stream at entry
    cudaEventRecord(e0, 0);
    cudaStreamWaitEvent(s2, e0, 0);

    // side stream: weight transposes (needed only at steps 6/7)
    transpose_cvt<float><<<dim3(D_FF / 32, D_MODEL / 32, 1), 256, 0, s2>>>(
        w1, w1t, D_MODEL, D_FF, 0, 0);
    transpose_cvt<float><<<dim3(D_MODEL / 32, D_FF / 32, 1), 256, 0, s2>>>(
        w2, w2t, D_FF, D_MODEL, 0, 0);

    // 1. norm1 = LN(src) -> fp16   (main stream)
    ln_kernel<<<NTOK, 256>>>(src, gamma1, beta1, norm1);
    cudaEventRecord(eLN, 0);

    // side stream: norm1t (needed only at step 4)
    cudaStreamWaitEvent(s2, eLN, 0);
    transpose_cvt<__half><<<dim3(D_MODEL / 32, SEQ / 32, BATCH), 256, 0, s2>>>(
        norm1, norm1t, SEQ, D_MODEL, SD, SD);
    cudaEventRecord(e1, s2);

    // 2. scores upper blocks + fused mirror (triangular grid: 136 pairs/batch)
    gemm_f16<0, 1, __half><<<dim3(136, 1, BATCH), 128>>>(
        norm1, norm1, scores, D_MODEL, SEQ, SD, SD, SS, nullptr, nullptr, 0.03125f);

    // 3. softmax rows
    softmax_kernel<<<BATCH * SEQ, 256>>>(scores);

    // join side stream before attn GEMM
    cudaStreamWaitEvent(0, e1, 0);

    // 4. x[b] = probs[b] @ norm1[b] + src[b]   (EPI 3, fused residual) -> fp32
    gemm_f16<3, 0, float><<<dim3(D_MODEL / 128, SEQ / 128, BATCH), 128>>>(
        scores, norm1t, x, SEQ, D_MODEL, SS, SD, SD, nullptr, src, 1.0f);

    // 5. norm2 = LN(x) -> fp16
    ln_kernel<<<NTOK, 256>>>(x, gamma2, beta2, norm2);

    // 6. h = gelu(norm2 @ w1 + b1)  (B = w1t) -> fp16
    gemm_f16<1, 0, __half><<<dim3(D_FF / 128, NTOK / 128, 1), 128>>>(
        norm2, w1t, h, D_MODEL, D_FF, 0, 0, 0, b1, nullptr, 1.0f);

    // 7. out = h @ w2 + b2 + x  (B = w2t) -> fp32
    gemm_f16<2, 0, float><<<dim3(D_MODEL / 128, NTOK / 128, 1), 128>>>(
        h, w2t, out, D_FF, D_MODEL, 0, 0, 0, b2, x, 1.0f);

    (void)in_sizes; (void)n_in; (void)out_size;
}